// round 6
// baseline (speedup 1.0000x reference)
#include <cuda_runtime.h>
#include <math.h>

// ---------------------------------------------------------------------------
// ESpaceLoss: biquad filter bank fwd+bwd -> tanh(W x) -> mean |p - t|
//
//   prep      : value-classified, dtype-robust coefficient load + analytic
//               fp64 reconstruction (validated against provided buffers)
//   kphi      : per-channel homogeneous tables psi1/psi2 (fp32) and chunk
//               transition matrix A = M^L (fp64), via binary powering.
//   pass1     : per (seq, chunk) zero-init particular recurrence (fp64),
//               stores valid-region y_p (fp32) and chunk end states E.
//   combine   : sequential 2x2 state propagation across chunks -> S
//   correction: y += psi1*s1 - psi2*(s1-s2)  (fp32, cancellation-free basis)
//   stageB    : out[o,t] = tanh(sum_c W[o,c] V[c,t]) for p and t, sum |diff|
//   finalize  : deterministic reduction -> scalar mean
// ---------------------------------------------------------------------------

#define TLEN   120000
#define LCH    1000
#define NCHUNK 80          // pass1 computes chunks 0..79 (rest never needed)
#define CH0    40          // first chunk overlapping the valid region
#define NCHV   40          // valid chunks: 40..79
#define MARGIN 40000
#define TV     40000       // valid samples per sequence
#define NC     64
#define NSEQ   16
#define TT     32          // stage B t-tile
#define NTB    (TV / TT)   // 1250
#define NPART  (NTB * 4)   // 5000

__device__ double g_c[3][NC];                  // a1, a2, b0 (normalized fp64)
__device__ double g_A[NC][4];                  // chunk transition M^L per channel
__device__ double g_E[NSEQ][NCHUNK][NC][2];    // particular end states
__device__ double g_S[NSEQ][NCHV][NC][2];      // exact init state per valid chunk
__device__ float  g_psi[LCH][NC][2];           // homogeneous basis (psi1, psi2)
__device__ float  g_Y[2 * 4 * TV * 128];       // [sig][b][t_local][dir*64+c]
__device__ double g_part[NPART];

// ---------------------------------------------------------------------------
// Coefficient prep.
// The three 64-elem buffers hold a1 (~-2), a2 (~1), b0 (~1e-5..5e-5) in SOME
// order and SOME dtype (float32 or float64). Classify each buffer by its
// first element under the f32 interpretation; if that is not coherent
// (one buffer per class), retry under the f64 interpretation. Then rebuild
// the exact fp64 coefficients analytically and validate; on match use the
// reconstruction, else the provided values.
// ---------------------------------------------------------------------------
__device__ __forceinline__ int coeff_class(double v) {
    if (!isfinite(v)) return -1;
    if (v > -2.5 && v < -1.5) return 0;       // a1
    if (v >  0.5 && v <  1.5) return 1;       // a2
    if (v > 1e-7 && v < 1e-2) return 2;       // b0
    return -1;
}

__global__ void __launch_bounds__(64) prep(const void* p0, const void* p1,
                                           const void* p2) {
    const void* bufs[3] = { p0, p1, p2 };
    int c = threadIdx.x;
    __shared__ int slot[3];
    __shared__ int use64;
    __shared__ int mism;

    if (c == 0) {
        int cf[3], cd[3];
        for (int k = 0; k < 3; ++k) {
            cf[k] = coeff_class((double)((const float*)bufs[k])[0]);
            cd[k] = coeff_class(((const double*)bufs[k])[0]);
        }
        bool okf = cf[0] >= 0 && cf[1] >= 0 && cf[2] >= 0 &&
                   cf[0] != cf[1] && cf[0] != cf[2] && cf[1] != cf[2];
        bool okd = cd[0] >= 0 && cd[1] >= 0 && cd[2] >= 0 &&
                   cd[0] != cd[1] && cd[0] != cd[2] && cd[1] != cd[2];
        use64 = okf ? 0 : 1;
        for (int k = 0; k < 3; ++k)
            slot[k] = okf ? cf[k] : (okd ? cd[k] : k);
        mism = 0;
    }
    __syncthreads();

    for (int k = 0; k < 3; ++k) {
        double v = use64 ? ((const double*)bufs[k])[c]
                         : (double)((const float*)bufs[k])[c];
        g_c[slot[k]][c] = v;
    }
    __syncthreads();

    // Analytic reconstruction (mirrors setup_inputs in fp64)
    const double PI = 3.14159265358979323846;
    double lmin = log(2.0 * PI * 10.0  / 24000.0);
    double lmax = log(2.0 * PI * 100.0 / 24000.0);
    double th = exp(lmin + (double)c * ((lmax - lmin) / 63.0));
    double r  = 0.9999 + (double)c * ((0.99999 - 0.9999) / 63.0);
    if (c == 63) { th = 2.0 * PI * 100.0 / 24000.0; r = 0.99999; }
    double ra1 = -2.0 * r * cos(th);
    double ra2 = r * r;
    double rb0 = (1.0 - r) * 0.5;

    if (fabs(ra1 - g_c[0][c]) > 1e-5 ||
        fabs(ra2 - g_c[1][c]) > 1e-5 ||
        fabs(rb0 - g_c[2][c]) > 1e-8)
        atomicOr(&mism, 1);
    __syncthreads();

    if (!mism) {
        g_c[0][c] = ra1;
        g_c[1][c] = ra2;
        g_c[2][c] = rb0;
    }
}

// ---------------------------------------------------------------------------
// Homogeneous tables + transition matrix. 512 threads: (channel, segment).
// phi1: init (y[-1],y[-2])=(1,0); phi2: init (0,1).
// psi1 = phi1+phi2, psi2 = phi2 (so y_hom = psi1*s1 - psi2*(s1-s2)).
// ---------------------------------------------------------------------------
__global__ void kphi() {
    int tid = threadIdx.x;
    int c   = tid & 63;
    int seg = tid >> 6;                 // 0..7, each covers 125 steps
    double m00 = -g_c[0][c], m01 = -g_c[1][c], m10 = 1.0, m11 = 0.0;

    // P = M^(seg*125) by binary powering
    double p00 = 1, p01 = 0, p10 = 0, p11 = 1;
    double b00 = m00, b01 = m01, b10 = m10, b11 = m11;
    int e = seg * 125;
    while (e) {
        if (e & 1) {
            double t00 = p00 * b00 + p01 * b10, t01 = p00 * b01 + p01 * b11;
            double t10 = p10 * b00 + p11 * b10, t11 = p10 * b01 + p11 * b11;
            p00 = t00; p01 = t01; p10 = t10; p11 = t11;
        }
        e >>= 1;
        if (e) {
            double t00 = b00 * b00 + b01 * b10, t01 = b00 * b01 + b01 * b11;
            double t10 = b10 * b00 + b11 * b10, t11 = b10 * b01 + b11 * b11;
            b00 = t00; b01 = t01; b10 = t10; b11 = t11;
        }
    }
    // state before step j0: phi1 -> (p00, p10), phi2 -> (p01, p11)
    double u1 = p00, u2 = p10, v1 = p01, v2 = p11;
    double na1 = m00, na2 = m01;
    int j0 = seg * 125;
    for (int j = j0; j < j0 + 125; ++j) {
        double yu = fma(na1, u1, na2 * u2);
        double yv = fma(na1, v1, na2 * v2);
        g_psi[j][c][0] = (float)(yu + yv);
        g_psi[j][c][1] = (float)yv;
        if (seg == 7) {
            if (j == LCH - 2) { g_A[c][2] = yu; g_A[c][3] = yv; }
            if (j == LCH - 1) { g_A[c][0] = yu; g_A[c][1] = yv; }
        }
        u2 = u1; u1 = yu;
        v2 = v1; v1 = yv;
    }
}

// ---------------------------------------------------------------------------
// Pass 1: zero-init particular recurrence per (seq, chunk).
// Block = 64 channels; x chunk staged in smem (broadcast reads).
// ---------------------------------------------------------------------------
__global__ void __launch_bounds__(64) pass1(
    const float* __restrict__ pred, const float* __restrict__ targ)
{
    int k = blockIdx.x;                  // chunk 0..79
    int s = blockIdx.y;                  // seq 0..15
    int sig = s >> 3, b = (s >> 1) & 3, dir = s & 1;
    const float* x = (sig ? targ : pred) + b * TLEN;

    __shared__ float xs[LCH];
    int k0 = k * LCH;
    if (dir == 0) {
        for (int j = threadIdx.x; j < LCH; j += 64) xs[j] = x[k0 + j];
    } else {
        for (int j = threadIdx.x; j < LCH; j += 64) xs[j] = x[TLEN - 1 - (k0 + j)];
    }
    __syncthreads();

    int c = threadIdx.x;
    double na1 = -g_c[0][c], na2 = -g_c[1][c];
    float b0f = (float)g_c[2][c];
    double y1 = 0.0, y2 = 0.0;

    if (k < CH0) {
        #pragma unroll 4
        for (int j = 0; j < LCH; ++j) {
            double y = fma(na1, y1, fma(na2, y2, (double)(b0f * xs[j])));
            y2 = y1; y1 = y;
        }
    } else {
        float* yrow = g_Y + (size_t)((sig * 4 + b) * TV) * 128 + dir * 64 + c;
        #pragma unroll 4
        for (int j = 0; j < LCH; ++j) {
            double y = fma(na1, y1, fma(na2, y2, (double)(b0f * xs[j])));
            int step = k0 + j;
            int tl = dir ? (TLEN - 1 - MARGIN - step) : (step - MARGIN);
            yrow[(size_t)tl * 128] = (float)y;
            y2 = y1; y1 = y;
        }
    }
    g_E[s][k][c][0] = y1;
    g_E[s][k][c][1] = y2;
}

// ---------------------------------------------------------------------------
// Sequential chunk-state propagation: s_{k+1} = A s_k + e_k, s_0 = 0.
// ---------------------------------------------------------------------------
__global__ void __launch_bounds__(64) combine() {
    int s = blockIdx.x;
    int c = threadIdx.x;
    double A00 = g_A[c][0], A01 = g_A[c][1], A10 = g_A[c][2], A11 = g_A[c][3];
    double s1 = 0.0, s2 = 0.0;
    for (int k = 0; k < NCHUNK; ++k) {
        if (k >= CH0) {
            g_S[s][k - CH0][c][0] = s1;
            g_S[s][k - CH0][c][1] = s2;
        }
        double e1 = g_E[s][k][c][0], e2 = g_E[s][k][c][1];
        double n1 = fma(A00, s1, fma(A01, s2, e1));
        double n2 = fma(A10, s1, fma(A11, s2, e2));
        s1 = n1; s2 = n2;
    }
}

// ---------------------------------------------------------------------------
// Correction: add homogeneous response of the exact init state (fp32).
// ---------------------------------------------------------------------------
__global__ void __launch_bounds__(64) correction() {
    int kk = blockIdx.x;                 // 0..39 -> chunk 40+kk
    int s  = blockIdx.y;
    int sig = s >> 3, b = (s >> 1) & 3, dir = s & 1;
    int c = threadIdx.x;

    double s1d = g_S[s][kk][c][0], s2d = g_S[s][kk][c][1];
    float d1 = (float)s1d;
    float d2 = (float)(s1d - s2d);

    float* yrow = g_Y + (size_t)((sig * 4 + b) * TV) * 128 + dir * 64 + c;
    int k0 = (CH0 + kk) * LCH;
    #pragma unroll 4
    for (int j = 0; j < LCH; ++j) {
        int step = k0 + j;
        int tl = dir ? (TLEN - 1 - MARGIN - step) : (step - MARGIN);
        float p1 = g_psi[j][c][0];
        float p2 = g_psi[j][c][1];
        float* p = yrow + (size_t)tl * 128;
        *p = *p + p1 * d1 - p2 * d2;
    }
}

// ---------------------------------------------------------------------------
// Stage B: emb = tanh(W @ v) for pred & target, accumulate |diff|.
// Block: 128 threads = 16 o-groups x 8 t-groups, each thread 4o x 4t x 2 sig.
// ---------------------------------------------------------------------------
__global__ void __launch_bounds__(128) stageB(const float* __restrict__ W) {
    extern __shared__ float sm[];
    float* Wsh = sm;                     // [128][65] (padded, [c][o])
    float* Vp  = sm + 128 * 65;          // [128][33] (padded, [c][tt])
    float* Vt  = Vp + 128 * 33;

    int tid = threadIdx.x;
    int b   = blockIdx.y;
    int t0  = blockIdx.x * TT;

    // W transposed into smem (coalesced global read, conflict-free smem write)
    for (int i = tid; i < 64 * 128; i += 128) {
        int c = i & 127, o = i >> 7;
        Wsh[c * 65 + o] = W[o * 128 + c];
    }
    const float* Yp = g_Y + (size_t)((0 * 4 + b) * TV + t0) * 128;
    const float* Yt = g_Y + (size_t)((1 * 4 + b) * TV + t0) * 128;
    for (int i = tid; i < TT * 128; i += 128) {
        int c = i & 127, tt = i >> 7;
        Vp[c * 33 + tt] = Yp[(size_t)tt * 128 + c];
        Vt[c * 33 + tt] = Yt[(size_t)tt * 128 + c];
    }
    __syncthreads();

    int og = tid >> 3;                   // 0..15 -> outputs og*4..+3
    int tg = tid & 7;                    // 0..7  -> t = t0 + tg*4..+3
    const float* wbase = Wsh + og * 4;
    const float* pbase = Vp + tg * 4;
    const float* tbase = Vt + tg * 4;

    float ap[4][4], at[4][4];
    #pragma unroll
    for (int i = 0; i < 4; ++i)
        #pragma unroll
        for (int j = 0; j < 4; ++j) { ap[i][j] = 0.f; at[i][j] = 0.f; }

    #pragma unroll 4
    for (int c = 0; c < 128; ++c) {
        float w0 = wbase[c * 65 + 0], w1 = wbase[c * 65 + 1];
        float w2 = wbase[c * 65 + 2], w3 = wbase[c * 65 + 3];
        float p0 = pbase[c * 33 + 0], p1 = pbase[c * 33 + 1];
        float p2 = pbase[c * 33 + 2], p3 = pbase[c * 33 + 3];
        float q0 = tbase[c * 33 + 0], q1 = tbase[c * 33 + 1];
        float q2 = tbase[c * 33 + 2], q3 = tbase[c * 33 + 3];
        ap[0][0] += w0 * p0; ap[0][1] += w0 * p1; ap[0][2] += w0 * p2; ap[0][3] += w0 * p3;
        ap[1][0] += w1 * p0; ap[1][1] += w1 * p1; ap[1][2] += w1 * p2; ap[1][3] += w1 * p3;
        ap[2][0] += w2 * p0; ap[2][1] += w2 * p1; ap[2][2] += w2 * p2; ap[2][3] += w2 * p3;
        ap[3][0] += w3 * p0; ap[3][1] += w3 * p1; ap[3][2] += w3 * p2; ap[3][3] += w3 * p3;
        at[0][0] += w0 * q0; at[0][1] += w0 * q1; at[0][2] += w0 * q2; at[0][3] += w0 * q3;
        at[1][0] += w1 * q0; at[1][1] += w1 * q1; at[1][2] += w1 * q2; at[1][3] += w1 * q3;
        at[2][0] += w2 * q0; at[2][1] += w2 * q1; at[2][2] += w2 * q2; at[2][3] += w2 * q3;
        at[3][0] += w3 * q0; at[3][1] += w3 * q1; at[3][2] += w3 * q2; at[3][3] += w3 * q3;
    }

    float lsum = 0.f;
    #pragma unroll
    for (int i = 0; i < 4; ++i)
        #pragma unroll
        for (int j = 0; j < 4; ++j)
            lsum += fabsf(tanhf(ap[i][j]) - tanhf(at[i][j]));

    #pragma unroll
    for (int off = 16; off; off >>= 1)
        lsum += __shfl_xor_sync(0xffffffffu, lsum, off);

    __shared__ float red[4];
    if ((tid & 31) == 0) red[tid >> 5] = lsum;
    __syncthreads();
    if (tid == 0)
        g_part[b * NTB + blockIdx.x] = (double)((red[0] + red[1]) + (red[2] + red[3]));
}

// ---------------------------------------------------------------------------
// Deterministic final reduction -> mean
// ---------------------------------------------------------------------------
__global__ void __launch_bounds__(256) finalize(float* out) {
    __shared__ double sd[256];
    double acc = 0.0;
    for (int i = threadIdx.x; i < NPART; i += 256) acc += g_part[i];
    sd[threadIdx.x] = acc;
    __syncthreads();
    for (int s = 128; s > 0; s >>= 1) {
        if (threadIdx.x < s) sd[threadIdx.x] += sd[threadIdx.x + s];
        __syncthreads();
    }
    if (threadIdx.x == 0)
        out[0] = (float)(sd[0] / (4.0 * 64.0 * 40000.0));
}

// ---------------------------------------------------------------------------
extern "C" void kernel_launch(void* const* d_in, const int* in_sizes, int n_in,
                              void* d_out, int out_size) {
    // Size-based dispatch; coefficient buffers are further classified BY VALUE
    // inside prep (so their order is irrelevant). pred/target order is
    // irrelevant (loss is symmetric in p,t).
    const float *pred = 0, *targ = 0, *W = 0;
    const void  *cf[3] = { 0, 0, 0 };
    int nBig = 0, nSmall = 0;
    for (int i = 0; i < n_in; ++i) {
        int sz = in_sizes[i];
        if (sz == 480000) {
            if (nBig == 0) pred = (const float*)d_in[i];
            else           targ = (const float*)d_in[i];
            ++nBig;
        } else if (sz == 64 && nSmall < 3) {
            cf[nSmall++] = d_in[i];
        } else if (sz == 8192) {
            W = (const float*)d_in[i];
        }
    }
    float* out = (float*)d_out;

    cudaFuncSetAttribute(stageB, cudaFuncAttributeMaxDynamicSharedMemorySize, 70000);

    prep<<<1, 64>>>(cf[0], cf[1], cf[2]);
    kphi<<<1, 512>>>();
    pass1<<<dim3(NCHUNK, NSEQ), 64>>>(pred, targ);
    combine<<<NSEQ, 64>>>();
    correction<<<dim3(NCHV, NSEQ), 64>>>();
    stageB<<<dim3(NTB, 4), 128, (128 * 65 + 2 * 128 * 33) * sizeof(float)>>>(W);
    finalize<<<1, 256>>>(out);
}

// round 7
// speedup vs baseline: 1.2421x; 1.2421x over previous
#include <cuda_runtime.h>
#include <math.h>

// ---------------------------------------------------------------------------
// ESpaceLoss: biquad filter bank fwd+bwd -> tanh(W x) -> mean |p - t|
//
//   prep    : value-classified, dtype-robust coefficient load + analytic
//             fp64 reconstruction (validated against provided buffers)
//   kphi    : homogeneous tables psi1/psi2 (fp32), impulse table F (fp32),
//             chunk transition matrix A = M^L (fp64), via binary powering.
//   pass1   : chunks 0..39: end states via fp32 dot products with F (fast);
//             chunks 40..79: fp64 recurrence, stores y_p (fp32) + end states.
//   combine : sequential 2x2 state propagation (prefetched) -> g_Sf (fp32)
//   stageB  : staging applies homogeneous correction, then f32x2 GEMM
//             with (pred,target) packed per lane-pair; accumulates |diff|.
//   finalize: deterministic reduction -> scalar mean
// ---------------------------------------------------------------------------

#define TLEN   120000
#define LCH    1000
#define NCHUNK 80
#define CH0    40
#define NCHV   40
#define MARGIN 40000
#define TV     40000
#define NC     64
#define NSEQ   16
#define TT     64          // stage B t-tile
#define NTB    (TV / TT)   // 625
#define NPART  (NTB * 4)   // 2500
#define WROW   65          // Wsh row stride (floats)
#define VROW   65          // V2 row stride (float2)

__device__ double g_c[3][NC];                  // a1, a2, b0 (normalized fp64)
__device__ double g_A[NC][4];                  // chunk transition M^L
__device__ double g_E[NSEQ][NCHUNK][NC][2];    // particular end states
__device__ float  g_Sf[NSEQ][NCHV][NC][2];     // (s1, s1-s2) per valid chunk
__device__ float  g_psi[LCH][NC][2];           // homogeneous basis (psi1, psi2)
__device__ float  g_F[LCH][NC];                // impulse table b0*f(m)
__device__ float  g_Y[2 * 4 * TV * 128];       // [sig][b][t_local][dir*64+c]
__device__ double g_part[NPART];

// ---------------------------------------------------------------------------
// Coefficient prep (dtype/order robust, validated analytic reconstruction)
// ---------------------------------------------------------------------------
__device__ __forceinline__ int coeff_class(double v) {
    if (!isfinite(v)) return -1;
    if (v > -2.5 && v < -1.5) return 0;       // a1
    if (v >  0.5 && v <  1.5) return 1;       // a2
    if (v > 1e-7 && v < 1e-2) return 2;       // b0
    return -1;
}

__global__ void __launch_bounds__(64) prep(const void* p0, const void* p1,
                                           const void* p2) {
    const void* bufs[3] = { p0, p1, p2 };
    int c = threadIdx.x;
    __shared__ int slot[3];
    __shared__ int use64;
    __shared__ int mism;

    if (c == 0) {
        int cf[3], cd[3];
        for (int k = 0; k < 3; ++k) {
            cf[k] = coeff_class((double)((const float*)bufs[k])[0]);
            cd[k] = coeff_class(((const double*)bufs[k])[0]);
        }
        bool okf = cf[0] >= 0 && cf[1] >= 0 && cf[2] >= 0 &&
                   cf[0] != cf[1] && cf[0] != cf[2] && cf[1] != cf[2];
        bool okd = cd[0] >= 0 && cd[1] >= 0 && cd[2] >= 0 &&
                   cd[0] != cd[1] && cd[0] != cd[2] && cd[1] != cd[2];
        use64 = okf ? 0 : 1;
        for (int k = 0; k < 3; ++k)
            slot[k] = okf ? cf[k] : (okd ? cd[k] : k);
        mism = 0;
    }
    __syncthreads();

    for (int k = 0; k < 3; ++k) {
        double v = use64 ? ((const double*)bufs[k])[c]
                         : (double)((const float*)bufs[k])[c];
        g_c[slot[k]][c] = v;
    }
    __syncthreads();

    const double PI = 3.14159265358979323846;
    double lmin = log(2.0 * PI * 10.0  / 24000.0);
    double lmax = log(2.0 * PI * 100.0 / 24000.0);
    double th = exp(lmin + (double)c * ((lmax - lmin) / 63.0));
    double r  = 0.9999 + (double)c * ((0.99999 - 0.9999) / 63.0);
    if (c == 63) { th = 2.0 * PI * 100.0 / 24000.0; r = 0.99999; }
    double ra1 = -2.0 * r * cos(th);
    double ra2 = r * r;
    double rb0 = (1.0 - r) * 0.5;

    if (fabs(ra1 - g_c[0][c]) > 1e-5 ||
        fabs(ra2 - g_c[1][c]) > 1e-5 ||
        fabs(rb0 - g_c[2][c]) > 1e-8)
        atomicOr(&mism, 1);
    __syncthreads();

    if (!mism) {
        g_c[0][c] = ra1;
        g_c[1][c] = ra2;
        g_c[2][c] = rb0;
    }
}

// ---------------------------------------------------------------------------
// Homogeneous + impulse tables and transition matrix.
// phi1(j): response to init (y-1,y-2)=(1,0); phi2: (0,1).
// psi1 = phi1+phi2, psi2 = phi2.  f(j) = (M^j)_00; phi1(j) = f(j+1).
// F[m] = b0 * f(m)  -> end states: y_999 = sum_m F[m] x_{999-m}.
// ---------------------------------------------------------------------------
__global__ void kphi() {
    int tid = threadIdx.x;
    int c   = tid & 63;
    int seg = tid >> 6;                 // 0..7, each 125 steps
    double m00 = -g_c[0][c], m01 = -g_c[1][c], m10 = 1.0, m11 = 0.0;
    float  b0f = (float)g_c[2][c];

    // P = M^(seg*125) by binary powering
    double p00 = 1, p01 = 0, p10 = 0, p11 = 1;
    double b00 = m00, b01 = m01, b10 = m10, b11 = m11;
    int e = seg * 125;
    while (e) {
        if (e & 1) {
            double t00 = p00 * b00 + p01 * b10, t01 = p00 * b01 + p01 * b11;
            double t10 = p10 * b00 + p11 * b10, t11 = p10 * b01 + p11 * b11;
            p00 = t00; p01 = t01; p10 = t10; p11 = t11;
        }
        e >>= 1;
        if (e) {
            double t00 = b00 * b00 + b01 * b10, t01 = b00 * b01 + b01 * b11;
            double t10 = b10 * b00 + b11 * b10, t11 = b10 * b01 + b11 * b11;
            b00 = t00; b01 = t01; b10 = t10; b11 = t11;
        }
    }
    if (seg == 0) g_F[0][c] = b0f;       // F[0] = b0 * f(0), f(0)=1

    double u1 = p00, u2 = p10, v1 = p01, v2 = p11;
    double na1 = m00, na2 = m01;
    int j0 = seg * 125;
    for (int j = j0; j < j0 + 125; ++j) {
        double yu = fma(na1, u1, na2 * u2);   // phi1(j) = f(j+1)
        double yv = fma(na1, v1, na2 * v2);   // phi2(j)
        g_psi[j][c][0] = (float)(yu + yv);
        g_psi[j][c][1] = (float)yv;
        if (j + 1 <= LCH - 1) g_F[j + 1][c] = b0f * (float)yu;
        if (seg == 7) {
            if (j == LCH - 2) { g_A[c][2] = yu; g_A[c][3] = yv; }
            if (j == LCH - 1) { g_A[c][0] = yu; g_A[c][1] = yv; }
        }
        u2 = u1; u1 = yu;
        v2 = v1; v1 = yv;
    }
}

// ---------------------------------------------------------------------------
// Pass 1. Chunks <40: fp32 dot products with F (end states only).
//         Chunks >=40: fp64 recurrence, stores y (fp32) + end states.
// ---------------------------------------------------------------------------
__global__ void __launch_bounds__(64) pass1(
    const float* __restrict__ pred, const float* __restrict__ targ)
{
    int k = blockIdx.x;                  // chunk 0..79
    int s = blockIdx.y;                  // seq 0..15
    int sig = s >> 3, b = (s >> 1) & 3, dir = s & 1;
    const float* x = (sig ? targ : pred) + b * TLEN;

    __shared__ float xs[LCH];
    int k0 = k * LCH;
    if (dir == 0) {
        for (int j = threadIdx.x; j < LCH; j += 64) xs[j] = x[k0 + j];
    } else {
        for (int j = threadIdx.x; j < LCH; j += 64) xs[j] = x[TLEN - 1 - (k0 + j)];
    }
    __syncthreads();

    int c = threadIdx.x;

    if (k < CH0) {
        // End states via dot products: e1 = sum_m F[m] x_{999-m},
        //                              e2 = sum_{m<=998} F[m] x_{998-m}
        float e1a = 0.f, e1b = 0.f, e2a = 0.f, e2b = 0.f;
        #pragma unroll 4
        for (int m = 0; m < 998; m += 2) {
            float f0 = g_F[m][c], f1 = g_F[m + 1][c];
            e1a += f0 * xs[999 - m];  e1b += f1 * xs[998 - m];
            e2a += f0 * xs[998 - m];  e2b += f1 * xs[997 - m];
        }
        {   // tails: m = 998 (e1,e2), m = 999 (e1 only)
            float f998 = g_F[998][c], f999 = g_F[999][c];
            e1a += f998 * xs[1];  e2a += f998 * xs[0];
            e1b += f999 * xs[0];
        }
        g_E[s][k][c][0] = (double)(e1a + e1b);
        g_E[s][k][c][1] = (double)(e2a + e2b);
    } else {
        double na1 = -g_c[0][c], na2 = -g_c[1][c];
        float b0f = (float)g_c[2][c];
        double y1 = 0.0, y2 = 0.0;
        float* yrow = g_Y + (size_t)((sig * 4 + b) * TV) * 128 + dir * 64 + c;
        #pragma unroll 4
        for (int j = 0; j < LCH; ++j) {
            double y = fma(na1, y1, fma(na2, y2, (double)(b0f * xs[j])));
            int step = k0 + j;
            int tl = dir ? (TLEN - 1 - MARGIN - step) : (step - MARGIN);
            yrow[(size_t)tl * 128] = (float)y;
            y2 = y1; y1 = y;
        }
        g_E[s][k][c][0] = y1;
        g_E[s][k][c][1] = y2;
    }
}

// ---------------------------------------------------------------------------
// Chunk-state propagation with batched prefetch (MLP=8 on the g_E loads).
// Writes fp32 (s1, s1-s2) for the fused correction in stageB.
// ---------------------------------------------------------------------------
__global__ void __launch_bounds__(64) combine() {
    int s = blockIdx.x;
    int c = threadIdx.x;
    double A00 = g_A[c][0], A01 = g_A[c][1], A10 = g_A[c][2], A11 = g_A[c][3];
    double s1 = 0.0, s2 = 0.0;
    for (int kb = 0; kb < NCHUNK; kb += 8) {
        double e[8][2];
        #pragma unroll
        for (int i = 0; i < 8; ++i) {
            e[i][0] = g_E[s][kb + i][c][0];
            e[i][1] = g_E[s][kb + i][c][1];
        }
        #pragma unroll
        for (int i = 0; i < 8; ++i) {
            int k = kb + i;
            if (k >= CH0) {
                g_Sf[s][k - CH0][c][0] = (float)s1;
                g_Sf[s][k - CH0][c][1] = (float)(s1 - s2);
            }
            double n1 = fma(A00, s1, fma(A01, s2, e[i][0]));
            double n2 = fma(A10, s1, fma(A11, s2, e[i][1]));
            s1 = n1; s2 = n2;
        }
    }
}

// ---------------------------------------------------------------------------
// Stage B: correction fused into smem staging, then f32x2 GEMM with
// (pred,target) packed per lane-pair. 128 thr = 16 o-groups x 8 t-groups,
// each thread 4o x 8t.
// ---------------------------------------------------------------------------
__device__ __forceinline__ unsigned long long pack2(float x) {
    unsigned long long r;
    asm("mov.b64 %0, {%1, %2};" : "=l"(r) : "f"(x), "f"(x));
    return r;
}
__device__ __forceinline__ void fma2(unsigned long long& d,
                                     unsigned long long a,
                                     unsigned long long b) {
    asm("fma.rn.f32x2 %0, %1, %2, %3;" : "=l"(d) : "l"(a), "l"(b), "l"(d));
}

__global__ void __launch_bounds__(128) stageB(const float* __restrict__ W) {
    extern __shared__ float sm[];
    float*  Wsh = sm;                               // [128][WROW]
    float2* V2  = (float2*)(sm + 128 * WROW);       // [128][VROW] (vp, vt)

    int tid = threadIdx.x;
    int b   = blockIdx.y;
    int t0  = blockIdx.x * TT;

    for (int i = tid; i < 64 * 128; i += 128) {
        int c = i & 127, o = i >> 7;
        Wsh[c * WROW + o] = W[o * 128 + c];
    }
    const float* Yp = g_Y + ((size_t)(0 * 4 + b) * TV + t0) * 128;
    const float* Yt = g_Y + ((size_t)(1 * 4 + b) * TV + t0) * 128;
    for (int i = tid; i < TT * 128; i += 128) {
        int c128 = i & 127, tt = i >> 7;
        int dir = c128 >> 6, c = c128 & 63;
        int t = t0 + tt;
        int step = dir ? (79999 - t) : (40000 + t);
        int kkg = step / 1000;
        int j = step - kkg * 1000;
        int kk = kkg - 40;
        float p1 = g_psi[j][c][0], p2 = g_psi[j][c][1];
        int sp = b * 2 + dir;        // sig = 0 (pred)
        int st = 8 + b * 2 + dir;    // sig = 1 (target)
        float vp = Yp[(size_t)tt * 128 + c128]
                 + p1 * g_Sf[sp][kk][c][0] - p2 * g_Sf[sp][kk][c][1];
        float vt = Yt[(size_t)tt * 128 + c128]
                 + p1 * g_Sf[st][kk][c][0] - p2 * g_Sf[st][kk][c][1];
        V2[c128 * VROW + tt] = make_float2(vp, vt);
    }
    __syncthreads();

    int og = tid >> 3;                   // 0..15 -> o = og*4..+3
    int tg = tid & 7;                    // 0..7  -> t = tg*8..+7
    const float* wb = Wsh + og * 4;
    const unsigned long long* vb =
        (const unsigned long long*)(V2 + tg * 8);

    unsigned long long acc[4][8];
    #pragma unroll
    for (int i = 0; i < 4; ++i)
        #pragma unroll
        for (int jj = 0; jj < 8; ++jj) acc[i][jj] = 0ull;

    #pragma unroll 2
    for (int c = 0; c < 128; ++c) {
        unsigned long long wp[4];
        #pragma unroll
        for (int i = 0; i < 4; ++i) wp[i] = pack2(wb[c * WROW + i]);
        unsigned long long v[8];
        #pragma unroll
        for (int jj = 0; jj < 8; ++jj) v[jj] = vb[c * VROW + jj];
        #pragma unroll
        for (int i = 0; i < 4; ++i)
            #pragma unroll
            for (int jj = 0; jj < 8; ++jj)
                fma2(acc[i][jj], wp[i], v[jj]);
    }

    float lsum = 0.f;
    #pragma unroll
    for (int i = 0; i < 4; ++i)
        #pragma unroll
        for (int jj = 0; jj < 8; ++jj) {
            float ps, ts;
            asm("mov.b64 {%0, %1}, %2;" : "=f"(ps), "=f"(ts) : "l"(acc[i][jj]));
            lsum += fabsf(tanhf(ps) - tanhf(ts));
        }

    #pragma unroll
    for (int off = 16; off; off >>= 1)
        lsum += __shfl_xor_sync(0xffffffffu, lsum, off);

    __shared__ float red[4];
    if ((tid & 31) == 0) red[tid >> 5] = lsum;
    __syncthreads();
    if (tid == 0)
        g_part[b * NTB + blockIdx.x] = (double)((red[0] + red[1]) + (red[2] + red[3]));
}

// ---------------------------------------------------------------------------
// Deterministic final reduction -> mean
// ---------------------------------------------------------------------------
__global__ void __launch_bounds__(256) finalize(float* out) {
    __shared__ double sd[256];
    double acc = 0.0;
    for (int i = threadIdx.x; i < NPART; i += 256) acc += g_part[i];
    sd[threadIdx.x] = acc;
    __syncthreads();
    for (int s = 128; s > 0; s >>= 1) {
        if (threadIdx.x < s) sd[threadIdx.x] += sd[threadIdx.x + s];
        __syncthreads();
    }
    if (threadIdx.x == 0)
        out[0] = (float)(sd[0] / (4.0 * 64.0 * 40000.0));
}

// ---------------------------------------------------------------------------
extern "C" void kernel_launch(void* const* d_in, const int* in_sizes, int n_in,
                              void* d_out, int out_size) {
    const float *pred = 0, *targ = 0, *W = 0;
    const void  *cf[3] = { 0, 0, 0 };
    int nBig = 0, nSmall = 0;
    for (int i = 0; i < n_in; ++i) {
        int sz = in_sizes[i];
        if (sz == 480000) {
            if (nBig == 0) pred = (const float*)d_in[i];
            else           targ = (const float*)d_in[i];
            ++nBig;
        } else if (sz == 64 && nSmall < 3) {
            cf[nSmall++] = d_in[i];
        } else if (sz == 8192) {
            W = (const float*)d_in[i];
        }
    }
    float* out = (float*)d_out;

    int smemB = 128 * WROW * 4 + 128 * VROW * 8;   // 99840 bytes
    cudaFuncSetAttribute(stageB, cudaFuncAttributeMaxDynamicSharedMemorySize,
                         smemB);

    prep<<<1, 64>>>(cf[0], cf[1], cf[2]);
    kphi<<<1, 512>>>();
    pass1<<<dim3(NCHUNK, NSEQ), 64>>>(pred, targ);
    combine<<<NSEQ, 64>>>();
    stageB<<<dim3(NTB, 4), 128, smemB>>>(W);
    finalize<<<1, 256>>>(out);
}

// round 8
// speedup vs baseline: 2.5898x; 2.0851x over previous
#include <cuda_runtime.h>
#include <math.h>

// ---------------------------------------------------------------------------
// ESpaceLoss: biquad filter bank fwd+bwd -> tanh(W x) -> mean |p - t|
//
//   prep      : value-classified, dtype-robust coefficient load + analytic
//               fp64 reconstruction (validated against provided buffers)
//   kphi_pass1: fused. Blocks 0..7: homogeneous tables psi (fp32) + chunk
//               transition A = M^L (fp64). Blocks 8..: per (seq,chunk)
//               zero-init fp32 recurrence (double-float coefficients),
//               stores valid-region y (fp32) + end states E.
//   combine   : sequential 2x2 fp64 state propagation -> g_Sf (fp32)
//   stageB    : staging applies homogeneous correction, then f32x2 GEMM
//               with (pred,target) packed per lane-pair; accumulates |diff|.
//   finalize  : deterministic reduction -> scalar mean
// ---------------------------------------------------------------------------

#define TLEN   120000
#define LCH    1000
#define NCHUNK 80
#define CH0    40
#define NCHV   40
#define MARGIN 40000
#define TV     40000
#define NC     64
#define NSEQ   16
#define TT     64          // stage B t-tile
#define NTB    (TV / TT)   // 625
#define NPART  (NTB * 4)   // 2500
#define WROW   65          // Wsh row stride (floats)
#define VROW   65          // V2 row stride (float2)

__device__ double g_c[3][NC];                  // a1, a2, b0 (normalized fp64)
__device__ double g_A[NC][4];                  // chunk transition M^L
__device__ double g_E[NSEQ][NCHUNK][NC][2];    // particular end states
__device__ float  g_Sf[NSEQ][NCHV][NC][2];     // (s1, s1-s2) per valid chunk
__device__ float  g_psi[LCH][NC][2];           // homogeneous basis (psi1, psi2)
__device__ float  g_Y[2 * 4 * TV * 128];       // [sig][b][t_local][dir*64+c]
__device__ double g_part[NPART];

// ---------------------------------------------------------------------------
// Coefficient prep (dtype/order robust, validated analytic reconstruction)
// ---------------------------------------------------------------------------
__device__ __forceinline__ int coeff_class(double v) {
    if (!isfinite(v)) return -1;
    if (v > -2.5 && v < -1.5) return 0;       // a1
    if (v >  0.5 && v <  1.5) return 1;       // a2
    if (v > 1e-7 && v < 1e-2) return 2;       // b0
    return -1;
}

__global__ void __launch_bounds__(64) prep(const void* p0, const void* p1,
                                           const void* p2) {
    const void* bufs[3] = { p0, p1, p2 };
    int c = threadIdx.x;
    __shared__ int slot[3];
    __shared__ int use64;
    __shared__ int mism;

    if (c == 0) {
        int cf[3], cd[3];
        for (int k = 0; k < 3; ++k) {
            cf[k] = coeff_class((double)((const float*)bufs[k])[0]);
            cd[k] = coeff_class(((const double*)bufs[k])[0]);
        }
        bool okf = cf[0] >= 0 && cf[1] >= 0 && cf[2] >= 0 &&
                   cf[0] != cf[1] && cf[0] != cf[2] && cf[1] != cf[2];
        bool okd = cd[0] >= 0 && cd[1] >= 0 && cd[2] >= 0 &&
                   cd[0] != cd[1] && cd[0] != cd[2] && cd[1] != cd[2];
        use64 = okf ? 0 : 1;
        for (int k = 0; k < 3; ++k)
            slot[k] = okf ? cf[k] : (okd ? cd[k] : k);
        mism = 0;
    }
    __syncthreads();

    for (int k = 0; k < 3; ++k) {
        double v = use64 ? ((const double*)bufs[k])[c]
                         : (double)((const float*)bufs[k])[c];
        g_c[slot[k]][c] = v;
    }
    __syncthreads();

    const double PI = 3.14159265358979323846;
    double lmin = log(2.0 * PI * 10.0  / 24000.0);
    double lmax = log(2.0 * PI * 100.0 / 24000.0);
    double th = exp(lmin + (double)c * ((lmax - lmin) / 63.0));
    double r  = 0.9999 + (double)c * ((0.99999 - 0.9999) / 63.0);
    if (c == 63) { th = 2.0 * PI * 100.0 / 24000.0; r = 0.99999; }
    double ra1 = -2.0 * r * cos(th);
    double ra2 = r * r;
    double rb0 = (1.0 - r) * 0.5;

    if (fabs(ra1 - g_c[0][c]) > 1e-5 ||
        fabs(ra2 - g_c[1][c]) > 1e-5 ||
        fabs(rb0 - g_c[2][c]) > 1e-8)
        atomicOr(&mism, 1);
    __syncthreads();

    if (!mism) {
        g_c[0][c] = ra1;
        g_c[1][c] = ra2;
        g_c[2][c] = rb0;
    }
}

// ---------------------------------------------------------------------------
// Fused kernel.
// Blocks 0..7  : psi tables (segment = blockIdx) + A from segment 7.
// Blocks 8..   : fp32 chunk recurrence (double-float coefficients).
// ---------------------------------------------------------------------------
__global__ void __launch_bounds__(64) kphi_pass1(
    const float* __restrict__ pred, const float* __restrict__ targ)
{
    __shared__ float xs[LCH];
    int c = threadIdx.x;

    if (blockIdx.x < 8) {
        // ---- psi segment ----
        int seg = blockIdx.x;
        double m00 = -g_c[0][c], m01 = -g_c[1][c];

        double p00 = 1, p01 = 0, p10 = 0, p11 = 1;
        double b00 = m00, b01 = m01, b10 = 1.0, b11 = 0.0;
        int e = seg * 125;
        while (e) {
            if (e & 1) {
                double t00 = p00 * b00 + p01 * b10, t01 = p00 * b01 + p01 * b11;
                double t10 = p10 * b00 + p11 * b10, t11 = p10 * b01 + p11 * b11;
                p00 = t00; p01 = t01; p10 = t10; p11 = t11;
            }
            e >>= 1;
            if (e) {
                double t00 = b00 * b00 + b01 * b10, t01 = b00 * b01 + b01 * b11;
                double t10 = b10 * b00 + b11 * b10, t11 = b10 * b01 + b11 * b11;
                b00 = t00; b01 = t01; b10 = t10; b11 = t11;
            }
        }
        double u1 = p00, u2 = p10, v1 = p01, v2 = p11;
        int j0 = seg * 125;
        for (int j = j0; j < j0 + 125; ++j) {
            double yu = fma(m00, u1, m01 * u2);   // phi1(j)
            double yv = fma(m00, v1, m01 * v2);   // phi2(j)
            g_psi[j][c][0] = (float)(yu + yv);
            g_psi[j][c][1] = (float)yv;
            if (seg == 7) {
                if (j == LCH - 2) { g_A[c][2] = yu; g_A[c][3] = yv; }
                if (j == LCH - 1) { g_A[c][0] = yu; g_A[c][1] = yv; }
            }
            u2 = u1; u1 = yu;
            v2 = v1; v1 = yv;
        }
        return;
    }

    // ---- fp32 chunk recurrence ----
    int idx = blockIdx.x - 8;
    int k = idx % NCHUNK;                // chunk 0..79
    int s = idx / NCHUNK;                // seq 0..15
    int sig = s >> 3, b = (s >> 1) & 3, dir = s & 1;
    const float* x = (sig ? targ : pred) + b * TLEN;

    int k0 = k * LCH;
    if (dir == 0) {
        for (int j = c; j < LCH; j += 64) xs[j] = x[k0 + j];
    } else {
        for (int j = c; j < LCH; j += 64) xs[j] = x[TLEN - 1 - (k0 + j)];
    }
    __syncthreads();

    // double-float coefficients: kills systematic pole-radius rounding bias
    double a1d = -g_c[0][c], a2d = -g_c[1][c];
    float na1h = (float)a1d;  float na1l = (float)(a1d - (double)na1h);
    float na2h = (float)a2d;  float na2l = (float)(a2d - (double)na2h);
    float b0f  = (float)g_c[2][c];

    float y1 = 0.f, y2 = 0.f;
    if (k < CH0) {
        #pragma unroll 4
        for (int j = 0; j < LCH; ++j) {
            float t = fmaf(na2l, y2, fmaf(na1l, y1, b0f * xs[j]));
            float y = fmaf(na1h, y1, fmaf(na2h, y2, t));
            y2 = y1; y1 = y;
        }
    } else {
        float* yrow = g_Y + (size_t)((sig * 4 + b) * TV) * 128 + dir * 64 + c;
        int tl0 = dir ? (TLEN - 1 - MARGIN - k0) : (k0 - MARGIN);
        int tstep = dir ? -1 : 1;
        #pragma unroll 4
        for (int j = 0; j < LCH; ++j) {
            float t = fmaf(na2l, y2, fmaf(na1l, y1, b0f * xs[j]));
            float y = fmaf(na1h, y1, fmaf(na2h, y2, t));
            yrow[(size_t)(tl0 + j * tstep) * 128] = y;
            y2 = y1; y1 = y;
        }
    }
    g_E[s][k][c][0] = (double)y1;
    g_E[s][k][c][1] = (double)y2;
}

// ---------------------------------------------------------------------------
// Chunk-state propagation with batched prefetch. Writes fp32 (s1, s1-s2).
// ---------------------------------------------------------------------------
__global__ void __launch_bounds__(64) combine() {
    int s = blockIdx.x;
    int c = threadIdx.x;
    double A00 = g_A[c][0], A01 = g_A[c][1], A10 = g_A[c][2], A11 = g_A[c][3];
    double s1 = 0.0, s2 = 0.0;
    for (int kb = 0; kb < NCHUNK; kb += 8) {
        double e[8][2];
        #pragma unroll
        for (int i = 0; i < 8; ++i) {
            e[i][0] = g_E[s][kb + i][c][0];
            e[i][1] = g_E[s][kb + i][c][1];
        }
        #pragma unroll
        for (int i = 0; i < 8; ++i) {
            int k = kb + i;
            if (k >= CH0) {
                g_Sf[s][k - CH0][c][0] = (float)s1;
                g_Sf[s][k - CH0][c][1] = (float)(s1 - s2);
            }
            double n1 = fma(A00, s1, fma(A01, s2, e[i][0]));
            double n2 = fma(A10, s1, fma(A11, s2, e[i][1]));
            s1 = n1; s2 = n2;
        }
    }
}

// ---------------------------------------------------------------------------
// Stage B: correction fused into smem staging, then f32x2 GEMM with
// (pred,target) packed per lane-pair. 128 thr = 16 o-groups x 8 t-groups,
// each thread 4o x 8t.
// ---------------------------------------------------------------------------
__device__ __forceinline__ unsigned long long pack2(float x) {
    unsigned long long r;
    asm("mov.b64 %0, {%1, %2};" : "=l"(r) : "f"(x), "f"(x));
    return r;
}
__device__ __forceinline__ void fma2(unsigned long long& d,
                                     unsigned long long a,
                                     unsigned long long b) {
    asm("fma.rn.f32x2 %0, %1, %2, %3;" : "=l"(d) : "l"(a), "l"(b), "l"(d));
}

__global__ void __launch_bounds__(128) stageB(const float* __restrict__ W) {
    extern __shared__ float sm[];
    float*  Wsh = sm;                               // [128][WROW]
    float2* V2  = (float2*)(sm + 128 * WROW);       // [128][VROW] (vp, vt)

    int tid = threadIdx.x;
    int b   = blockIdx.y;
    int t0  = blockIdx.x * TT;

    for (int i = tid; i < 64 * 128; i += 128) {
        int c = i & 127, o = i >> 7;
        Wsh[c * WROW + o] = W[o * 128 + c];
    }
    const float* Yp = g_Y + ((size_t)(0 * 4 + b) * TV + t0) * 128;
    const float* Yt = g_Y + ((size_t)(1 * 4 + b) * TV + t0) * 128;
    for (int i = tid; i < TT * 128; i += 128) {
        int c128 = i & 127, tt = i >> 7;
        int dir = c128 >> 6, c = c128 & 63;
        int t = t0 + tt;
        int step = dir ? (79999 - t) : (40000 + t);
        int kkg = step / 1000;
        int j = step - kkg * 1000;
        int kk = kkg - 40;
        float p1 = g_psi[j][c][0], p2 = g_psi[j][c][1];
        int sp = b * 2 + dir;        // sig = 0 (pred)
        int st = 8 + b * 2 + dir;    // sig = 1 (target)
        float vp = Yp[(size_t)tt * 128 + c128]
                 + p1 * g_Sf[sp][kk][c][0] - p2 * g_Sf[sp][kk][c][1];
        float vt = Yt[(size_t)tt * 128 + c128]
                 + p1 * g_Sf[st][kk][c][0] - p2 * g_Sf[st][kk][c][1];
        V2[c128 * VROW + tt] = make_float2(vp, vt);
    }
    __syncthreads();

    int og = tid >> 3;                   // 0..15 -> o = og*4..+3
    int tg = tid & 7;                    // 0..7  -> t = tg*8..+7
    const float* wb = Wsh + og * 4;
    const unsigned long long* vb =
        (const unsigned long long*)(V2 + tg * 8);

    unsigned long long acc[4][8];
    #pragma unroll
    for (int i = 0; i < 4; ++i)
        #pragma unroll
        for (int jj = 0; jj < 8; ++jj) acc[i][jj] = 0ull;

    #pragma unroll 2
    for (int c = 0; c < 128; ++c) {
        unsigned long long wp[4];
        #pragma unroll
        for (int i = 0; i < 4; ++i) wp[i] = pack2(wb[c * WROW + i]);
        unsigned long long v[8];
        #pragma unroll
        for (int jj = 0; jj < 8; ++jj) v[jj] = vb[c * VROW + jj];
        #pragma unroll
        for (int i = 0; i < 4; ++i)
            #pragma unroll
            for (int jj = 0; jj < 8; ++jj)
                fma2(acc[i][jj], wp[i], v[jj]);
    }

    float lsum = 0.f;
    #pragma unroll
    for (int i = 0; i < 4; ++i)
        #pragma unroll
        for (int jj = 0; jj < 8; ++jj) {
            float ps, ts;
            asm("mov.b64 {%0, %1}, %2;" : "=f"(ps), "=f"(ts) : "l"(acc[i][jj]));
            lsum += fabsf(tanhf(ps) - tanhf(ts));
        }

    #pragma unroll
    for (int off = 16; off; off >>= 1)
        lsum += __shfl_xor_sync(0xffffffffu, lsum, off);

    __shared__ float red[4];
    if ((tid & 31) == 0) red[tid >> 5] = lsum;
    __syncthreads();
    if (tid == 0)
        g_part[b * NTB + blockIdx.x] = (double)((red[0] + red[1]) + (red[2] + red[3]));
}

// ---------------------------------------------------------------------------
// Deterministic final reduction -> mean
// ---------------------------------------------------------------------------
__global__ void __launch_bounds__(256) finalize(float* out) {
    __shared__ double sd[256];
    double acc = 0.0;
    for (int i = threadIdx.x; i < NPART; i += 256) acc += g_part[i];
    sd[threadIdx.x] = acc;
    __syncthreads();
    for (int s = 128; s > 0; s >>= 1) {
        if (threadIdx.x < s) sd[threadIdx.x] += sd[threadIdx.x + s];
        __syncthreads();
    }
    if (threadIdx.x == 0)
        out[0] = (float)(sd[0] / (4.0 * 64.0 * 40000.0));
}

// ---------------------------------------------------------------------------
extern "C" void kernel_launch(void* const* d_in, const int* in_sizes, int n_in,
                              void* d_out, int out_size) {
    const float *pred = 0, *targ = 0, *W = 0;
    const void  *cf[3] = { 0, 0, 0 };
    int nBig = 0, nSmall = 0;
    for (int i = 0; i < n_in; ++i) {
        int sz = in_sizes[i];
        if (sz == 480000) {
            if (nBig == 0) pred = (const float*)d_in[i];
            else           targ = (const float*)d_in[i];
            ++nBig;
        } else if (sz == 64 && nSmall < 3) {
            cf[nSmall++] = d_in[i];
        } else if (sz == 8192) {
            W = (const float*)d_in[i];
        }
    }
    float* out = (float*)d_out;

    int smemB = 128 * WROW * 4 + 128 * VROW * 8;   // 99840 bytes
    cudaFuncSetAttribute(stageB, cudaFuncAttributeMaxDynamicSharedMemorySize,
                         smemB);

    prep<<<1, 64>>>(cf[0], cf[1], cf[2]);
    kphi_pass1<<<8 + NCHUNK * NSEQ, 64>>>(pred, targ);
    combine<<<NSEQ, 64>>>();
    stageB<<<dim3(NTB, 4), 128, smemB>>>(W);
    finalize<<<1, 256>>>(out);
}

// round 9
// speedup vs baseline: 3.3332x; 1.2870x over previous
#include <cuda_runtime.h>
#include <math.h>

// ---------------------------------------------------------------------------
// ESpaceLoss: biquad filter bank fwd+bwd -> tanh(W x) -> mean |p - t|
//
//   prep      : value-classified, dtype-robust coefficient load + analytic
//               fp64 reconstruction (validated against provided buffers)
//   kphi_pass1: fused. Blocks 0..7: homogeneous tables psi (fp32) + chunk
//               transition A = M^L (fp64). Blocks 8..: per (seq,chunk)
//               zero-init fp32 recurrence (double-float coefficients),
//               stores valid-region y (fp32) + end states E.
//   combine   : sequential 2x2 fp64 state propagation -> g_Sf (fp32)
//   stageB    : two c-phases; staging applies homogeneous correction with a
//               bank-swizzled V layout; 128-bit LDS + f32x2 GEMM; tanh.approx
//               epilogue; accumulates |diff|.
//   finalize  : deterministic reduction -> scalar mean
// ---------------------------------------------------------------------------

#define TLEN   120000
#define LCH    1000
#define NCHUNK 80
#define CH0    40
#define NCHV   40
#define MARGIN 40000
#define TV     40000
#define NC     64
#define NSEQ   16
#define TT     64          // stage B t-tile
#define NTB    (TV / TT)   // 625
#define NPART  (NTB * 4)   // 2500
#define WROW   68          // Wsh row stride (floats); 272B = 17 16B-lines (odd)
#define VROW2  66          // V2 row stride (float2); 528B = 33 16B-lines (odd)
#define SMEM_B (64 * WROW * 4 + 64 * VROW2 * 8)   // 17408 + 33792 = 51200

__device__ double g_c[3][NC];                  // a1, a2, b0 (normalized fp64)
__device__ double g_A[NC][4];                  // chunk transition M^L
__device__ double g_E[NSEQ][NCHUNK][NC][2];    // particular end states
__device__ float  g_Sf[NSEQ][NCHV][NC][2];     // (s1, s1-s2) per valid chunk
__device__ float  g_psi[LCH][NC][2];           // homogeneous basis (psi1, psi2)
__device__ float  g_Y[2 * 4 * TV * 128];       // [sig][b][t_local][dir*64+c]
__device__ double g_part[NPART];

// ---------------------------------------------------------------------------
// Coefficient prep (dtype/order robust, validated analytic reconstruction)
// ---------------------------------------------------------------------------
__device__ __forceinline__ int coeff_class(double v) {
    if (!isfinite(v)) return -1;
    if (v > -2.5 && v < -1.5) return 0;       // a1
    if (v >  0.5 && v <  1.5) return 1;       // a2
    if (v > 1e-7 && v < 1e-2) return 2;       // b0
    return -1;
}

__global__ void __launch_bounds__(64) prep(const void* p0, const void* p1,
                                           const void* p2) {
    const void* bufs[3] = { p0, p1, p2 };
    int c = threadIdx.x;
    __shared__ int slot[3];
    __shared__ int use64;
    __shared__ int mism;

    if (c == 0) {
        int cf[3], cd[3];
        for (int k = 0; k < 3; ++k) {
            cf[k] = coeff_class((double)((const float*)bufs[k])[0]);
            cd[k] = coeff_class(((const double*)bufs[k])[0]);
        }
        bool okf = cf[0] >= 0 && cf[1] >= 0 && cf[2] >= 0 &&
                   cf[0] != cf[1] && cf[0] != cf[2] && cf[1] != cf[2];
        bool okd = cd[0] >= 0 && cd[1] >= 0 && cd[2] >= 0 &&
                   cd[0] != cd[1] && cd[0] != cd[2] && cd[1] != cd[2];
        use64 = okf ? 0 : 1;
        for (int k = 0; k < 3; ++k)
            slot[k] = okf ? cf[k] : (okd ? cd[k] : k);
        mism = 0;
    }
    __syncthreads();

    for (int k = 0; k < 3; ++k) {
        double v = use64 ? ((const double*)bufs[k])[c]
                         : (double)((const float*)bufs[k])[c];
        g_c[slot[k]][c] = v;
    }
    __syncthreads();

    const double PI = 3.14159265358979323846;
    double lmin = log(2.0 * PI * 10.0  / 24000.0);
    double lmax = log(2.0 * PI * 100.0 / 24000.0);
    double th = exp(lmin + (double)c * ((lmax - lmin) / 63.0));
    double r  = 0.9999 + (double)c * ((0.99999 - 0.9999) / 63.0);
    if (c == 63) { th = 2.0 * PI * 100.0 / 24000.0; r = 0.99999; }
    double ra1 = -2.0 * r * cos(th);
    double ra2 = r * r;
    double rb0 = (1.0 - r) * 0.5;

    if (fabs(ra1 - g_c[0][c]) > 1e-5 ||
        fabs(ra2 - g_c[1][c]) > 1e-5 ||
        fabs(rb0 - g_c[2][c]) > 1e-8)
        atomicOr(&mism, 1);
    __syncthreads();

    if (!mism) {
        g_c[0][c] = ra1;
        g_c[1][c] = ra2;
        g_c[2][c] = rb0;
    }
}

// ---------------------------------------------------------------------------
// Fused kernel. Blocks 0..7: psi segments + A. Blocks 8..: fp32 recurrence.
// ---------------------------------------------------------------------------
__global__ void __launch_bounds__(64) kphi_pass1(
    const float* __restrict__ pred, const float* __restrict__ targ)
{
    __shared__ float xs[LCH];
    int c = threadIdx.x;

    if (blockIdx.x < 8) {
        int seg = blockIdx.x;
        double m00 = -g_c[0][c], m01 = -g_c[1][c];

        double p00 = 1, p01 = 0, p10 = 0, p11 = 1;
        double b00 = m00, b01 = m01, b10 = 1.0, b11 = 0.0;
        int e = seg * 125;
        while (e) {
            if (e & 1) {
                double t00 = p00 * b00 + p01 * b10, t01 = p00 * b01 + p01 * b11;
                double t10 = p10 * b00 + p11 * b10, t11 = p10 * b01 + p11 * b11;
                p00 = t00; p01 = t01; p10 = t10; p11 = t11;
            }
            e >>= 1;
            if (e) {
                double t00 = b00 * b00 + b01 * b10, t01 = b00 * b01 + b01 * b11;
                double t10 = b10 * b00 + b11 * b10, t11 = b10 * b01 + b11 * b11;
                b00 = t00; b01 = t01; b10 = t10; b11 = t11;
            }
        }
        double u1 = p00, u2 = p10, v1 = p01, v2 = p11;
        int j0 = seg * 125;
        for (int j = j0; j < j0 + 125; ++j) {
            double yu = fma(m00, u1, m01 * u2);
            double yv = fma(m00, v1, m01 * v2);
            g_psi[j][c][0] = (float)(yu + yv);
            g_psi[j][c][1] = (float)yv;
            if (seg == 7) {
                if (j == LCH - 2) { g_A[c][2] = yu; g_A[c][3] = yv; }
                if (j == LCH - 1) { g_A[c][0] = yu; g_A[c][1] = yv; }
            }
            u2 = u1; u1 = yu;
            v2 = v1; v1 = yv;
        }
        return;
    }

    int idx = blockIdx.x - 8;
    int k = idx % NCHUNK;
    int s = idx / NCHUNK;
    int sig = s >> 3, b = (s >> 1) & 3, dir = s & 1;
    const float* x = (sig ? targ : pred) + b * TLEN;

    int k0 = k * LCH;
    if (dir == 0) {
        for (int j = c; j < LCH; j += 64) xs[j] = x[k0 + j];
    } else {
        for (int j = c; j < LCH; j += 64) xs[j] = x[TLEN - 1 - (k0 + j)];
    }
    __syncthreads();

    double a1d = -g_c[0][c], a2d = -g_c[1][c];
    float na1h = (float)a1d;  float na1l = (float)(a1d - (double)na1h);
    float na2h = (float)a2d;  float na2l = (float)(a2d - (double)na2h);
    float b0f  = (float)g_c[2][c];

    float y1 = 0.f, y2 = 0.f;
    if (k < CH0) {
        #pragma unroll 4
        for (int j = 0; j < LCH; ++j) {
            float t = fmaf(na2l, y2, fmaf(na1l, y1, b0f * xs[j]));
            float y = fmaf(na1h, y1, fmaf(na2h, y2, t));
            y2 = y1; y1 = y;
        }
    } else {
        float* yrow = g_Y + (size_t)((sig * 4 + b) * TV) * 128 + dir * 64 + c;
        int tl0 = dir ? (TLEN - 1 - MARGIN - k0) : (k0 - MARGIN);
        int tstep = dir ? -1 : 1;
        #pragma unroll 4
        for (int j = 0; j < LCH; ++j) {
            float t = fmaf(na2l, y2, fmaf(na1l, y1, b0f * xs[j]));
            float y = fmaf(na1h, y1, fmaf(na2h, y2, t));
            yrow[(size_t)(tl0 + j * tstep) * 128] = y;
            y2 = y1; y1 = y;
        }
    }
    g_E[s][k][c][0] = (double)y1;
    g_E[s][k][c][1] = (double)y2;
}

// ---------------------------------------------------------------------------
// Chunk-state propagation with batched prefetch. Writes fp32 (s1, s1-s2).
// ---------------------------------------------------------------------------
__global__ void __launch_bounds__(64) combine() {
    int s = blockIdx.x;
    int c = threadIdx.x;
    double A00 = g_A[c][0], A01 = g_A[c][1], A10 = g_A[c][2], A11 = g_A[c][3];
    double s1 = 0.0, s2 = 0.0;
    for (int kb = 0; kb < NCHUNK; kb += 8) {
        double e[8][2];
        #pragma unroll
        for (int i = 0; i < 8; ++i) {
            e[i][0] = g_E[s][kb + i][c][0];
            e[i][1] = g_E[s][kb + i][c][1];
        }
        #pragma unroll
        for (int i = 0; i < 8; ++i) {
            int k = kb + i;
            if (k >= CH0) {
                g_Sf[s][k - CH0][c][0] = (float)s1;
                g_Sf[s][k - CH0][c][1] = (float)(s1 - s2);
            }
            double n1 = fma(A00, s1, fma(A01, s2, e[i][0]));
            double n2 = fma(A10, s1, fma(A11, s2, e[i][1]));
            s1 = n1; s2 = n2;
        }
    }
}

// ---------------------------------------------------------------------------
// Stage B helpers
// ---------------------------------------------------------------------------
__device__ __forceinline__ unsigned long long pack2(float x) {
    unsigned long long r;
    asm("mov.b64 %0, {%1, %2};" : "=l"(r) : "f"(x), "f"(x));
    return r;
}
__device__ __forceinline__ void fma2(unsigned long long& d,
                                     unsigned long long a,
                                     unsigned long long b) {
    asm("fma.rn.f32x2 %0, %1, %2, %3;" : "=l"(d) : "l"(a), "l"(b), "l"(d));
}
__device__ __forceinline__ float tanh_fast(float x) {
    float r;
    asm("tanh.approx.f32 %0, %1;" : "=f"(r) : "f"(x));
    return r;
}

// Stage B: 128 thr = 16 o-groups x 8 t-groups, each thread 4o x 8t, two
// 64-wide c-phases. V rows are line-swizzled so the four 128-bit v loads
// per c are bank-conflict-free across the 8 t-groups.
__global__ void __launch_bounds__(128, 4) stageB(const float* __restrict__ W) {
    extern __shared__ float sm[];
    float*  Wsh = sm;                               // [64][WROW]
    float2* V2  = (float2*)(sm + 64 * WROW);        // [64][VROW2] swizzled

    int tid = threadIdx.x;
    int b   = blockIdx.y;
    int t0  = blockIdx.x * TT;
    int og  = tid >> 3;                  // 0..15 -> o = og*4..+3
    int tg  = tid & 7;                   // 0..7  -> t = tg*8..+7

    const float* Yp = g_Y + ((size_t)(0 * 4 + b) * TV + t0) * 128;
    const float* Yt = g_Y + ((size_t)(1 * 4 + b) * TV + t0) * 128;

    unsigned int w_base = (unsigned int)__cvta_generic_to_shared(Wsh) + og * 16;
    unsigned int v_base = (unsigned int)__cvta_generic_to_shared(V2);
    unsigned int v_off[4];
    #pragma unroll
    for (int jj = 0; jj < 4; ++jj)
        v_off[jj] = (unsigned)(4 * ((tg + jj) & 7) + jj) * 16;

    unsigned long long acc[4][8];
    #pragma unroll
    for (int i = 0; i < 4; ++i)
        #pragma unroll
        for (int jj = 0; jj < 8; ++jj) acc[i][jj] = 0ull;

    for (int ph = 0; ph < 2; ++ph) {
        int cbase = ph * 64;

        // stage W chunk [64c x 64o], c-contiguous global reads
        for (int i = tid; i < 64 * 64; i += 128) {
            int cc = i & 63, o = i >> 6;
            Wsh[cc * WROW + o] = W[o * 128 + cbase + cc];
        }
        // stage V chunk with fused homogeneous correction + line swizzle
        for (int i = tid; i < TT * 64; i += 128) {
            int cc = i & 63, tt = i >> 6;
            int c128 = cbase + cc;
            int dir = c128 >> 6, c = c128 & 63;
            int t = t0 + tt;
            int step = dir ? (79999 - t) : (40000 + t);
            int kkg = step / 1000;
            int j = step - kkg * 1000;
            int kk = kkg - 40;
            float p1 = g_psi[j][c][0], p2 = g_psi[j][c][1];
            int sp = b * 2 + dir;
            int st = 8 + b * 2 + dir;
            float vp = Yp[(size_t)tt * 128 + c128]
                     + p1 * g_Sf[sp][kk][c][0] - p2 * g_Sf[sp][kk][c][1];
            float vt = Yt[(size_t)tt * 128 + c128]
                     + p1 * g_Sf[st][kk][c][0] - p2 * g_Sf[st][kk][c][1];
            int l = tt >> 1, e = tt & 1;
            int lp = 4 * (((l >> 2) + (l & 3)) & 7) + (l & 3);
            V2[cc * VROW2 + lp * 2 + e] = make_float2(vp, vt);
        }
        __syncthreads();

        #pragma unroll 2
        for (int cc = 0; cc < 64; ++cc) {
            float w0, w1, w2, w3;
            asm("ld.shared.v4.f32 {%0,%1,%2,%3}, [%4];"
                : "=f"(w0), "=f"(w1), "=f"(w2), "=f"(w3)
                : "r"(w_base + (unsigned)cc * (WROW * 4)));
            unsigned long long wp[4] = { pack2(w0), pack2(w1),
                                         pack2(w2), pack2(w3) };
            unsigned int vrow = v_base + (unsigned)cc * (VROW2 * 8);
            #pragma unroll
            for (int jj = 0; jj < 4; ++jj) {
                unsigned long long va, vb;
                asm("ld.shared.v2.b64 {%0,%1}, [%2];"
                    : "=l"(va), "=l"(vb) : "r"(vrow + v_off[jj]));
                #pragma unroll
                for (int i = 0; i < 4; ++i) {
                    fma2(acc[i][2 * jj + 0], wp[i], va);
                    fma2(acc[i][2 * jj + 1], wp[i], vb);
                }
            }
        }
        __syncthreads();
    }

    float lsum = 0.f;
    #pragma unroll
    for (int i = 0; i < 4; ++i)
        #pragma unroll
        for (int jj = 0; jj < 8; ++jj) {
            float ps, ts;
            asm("mov.b64 {%0, %1}, %2;" : "=f"(ps), "=f"(ts) : "l"(acc[i][jj]));
            lsum += fabsf(tanh_fast(ps) - tanh_fast(ts));
        }

    #pragma unroll
    for (int off = 16; off; off >>= 1)
        lsum += __shfl_xor_sync(0xffffffffu, lsum, off);

    __shared__ float red[4];
    if ((tid & 31) == 0) red[tid >> 5] = lsum;
    __syncthreads();
    if (tid == 0)
        g_part[b * NTB + blockIdx.x] = (double)((red[0] + red[1]) + (red[2] + red[3]));
}

// ---------------------------------------------------------------------------
// Deterministic final reduction -> mean
// ---------------------------------------------------------------------------
__global__ void __launch_bounds__(256) finalize(float* out) {
    __shared__ double sd[256];
    double acc = 0.0;
    for (int i = threadIdx.x; i < NPART; i += 256) acc += g_part[i];
    sd[threadIdx.x] = acc;
    __syncthreads();
    for (int s = 128; s > 0; s >>= 1) {
        if (threadIdx.x < s) sd[threadIdx.x] += sd[threadIdx.x + s];
        __syncthreads();
    }
    if (threadIdx.x == 0)
        out[0] = (float)(sd[0] / (4.0 * 64.0 * 40000.0));
}

// ---------------------------------------------------------------------------
extern "C" void kernel_launch(void* const* d_in, const int* in_sizes, int n_in,
                              void* d_out, int out_size) {
    const float *pred = 0, *targ = 0, *W = 0;
    const void  *cf[3] = { 0, 0, 0 };
    int nBig = 0, nSmall = 0;
    for (int i = 0; i < n_in; ++i) {
        int sz = in_sizes[i];
        if (sz == 480000) {
            if (nBig == 0) pred = (const float*)d_in[i];
            else           targ = (const float*)d_in[i];
            ++nBig;
        } else if (sz == 64 && nSmall < 3) {
            cf[nSmall++] = d_in[i];
        } else if (sz == 8192) {
            W = (const float*)d_in[i];
        }
    }
    float* out = (float*)d_out;

    cudaFuncSetAttribute(stageB, cudaFuncAttributeMaxDynamicSharedMemorySize,
                         SMEM_B);

    prep<<<1, 64>>>(cf[0], cf[1], cf[2]);
    kphi_pass1<<<8 + NCHUNK * NSEQ, 64>>>(pred, targ);
    combine<<<NSEQ, 64>>>();
    stageB<<<dim3(NTB, 4), 128, SMEM_B>>>(W);
    finalize<<<1, 256>>>(out);
}

// round 10
// speedup vs baseline: 7.7695x; 2.3310x over previous
#include <cuda_runtime.h>
#include <cuda_bf16.h>
#include <math.h>

// ---------------------------------------------------------------------------
// ESpaceLoss: biquad filter bank fwd+bwd -> tanh(W x) -> mean |p - t|
//
//   prep      : value-classified, dtype-robust coefficient load + analytic
//               fp64 reconstruction (validated against provided buffers)
//   kphi_pass1: fused. Blocks 0..7: psi tables + chunk transition A.
//               Blocks 8..: fp32 recurrence (double-float coeffs), stores
//               valid-region y as bf16 + end states E.
//   combine   : sequential 2x2 fp64 state propagation -> g_Sf (fp32)
//   stageB    : staging applies homogeneous correction via per-row recurrence
//               (no table loads in loop), packs bf16 tiles; bf16 mma.sync
//               tensor-core GEMM for both signals; tanh.approx + |diff| sum.
//   finalize  : deterministic reduction -> scalar mean
// ---------------------------------------------------------------------------

#define TLEN   120000
#define LCH    1000
#define NCHUNK 80
#define CH0    40
#define NCHV   40
#define MARGIN 40000
#define TV     40000
#define NC     64
#define NSEQ   16
#define TT     64          // stage B t-tile
#define NTB    (TV / TT)   // 625
#define NPART  (NTB * 4)   // 2500

#define ROWB   272                     // bf16 tile row stride in bytes (17 lines)
#define WBYTES (64 * ROWB)             // 17408
#define VSIGB  (64 * ROWB)             // 17408 per signal
#define SMEM_B (WBYTES + 2 * VSIGB)    // 52224

__device__ double g_c[3][NC];                  // a1, a2, b0 (normalized fp64)
__device__ double g_A[NC][4];                  // chunk transition M^L
__device__ double g_E[NSEQ][NCHUNK][NC][2];    // particular end states
__device__ float  g_Sf[NSEQ][NCHV][NC][2];     // (s1, s1-s2) per valid chunk
__device__ float  g_psi[LCH][NC][2];           // homogeneous basis (psi1, psi2)
__device__ __nv_bfloat16 g_Yh[(size_t)2 * 4 * TV * 128]; // [sig][b][t][dir*64+c]
__device__ double g_part[NPART];

// ---------------------------------------------------------------------------
// Coefficient prep (dtype/order robust, validated analytic reconstruction)
// ---------------------------------------------------------------------------
__device__ __forceinline__ int coeff_class(double v) {
    if (!isfinite(v)) return -1;
    if (v > -2.5 && v < -1.5) return 0;       // a1
    if (v >  0.5 && v <  1.5) return 1;       // a2
    if (v > 1e-7 && v < 1e-2) return 2;       // b0
    return -1;
}

__global__ void __launch_bounds__(64) prep(const void* p0, const void* p1,
                                           const void* p2) {
    const void* bufs[3] = { p0, p1, p2 };
    int c = threadIdx.x;
    __shared__ int slot[3];
    __shared__ int use64;
    __shared__ int mism;

    if (c == 0) {
        int cf[3], cd[3];
        for (int k = 0; k < 3; ++k) {
            cf[k] = coeff_class((double)((const float*)bufs[k])[0]);
            cd[k] = coeff_class(((const double*)bufs[k])[0]);
        }
        bool okf = cf[0] >= 0 && cf[1] >= 0 && cf[2] >= 0 &&
                   cf[0] != cf[1] && cf[0] != cf[2] && cf[1] != cf[2];
        bool okd = cd[0] >= 0 && cd[1] >= 0 && cd[2] >= 0 &&
                   cd[0] != cd[1] && cd[0] != cd[2] && cd[1] != cd[2];
        use64 = okf ? 0 : 1;
        for (int k = 0; k < 3; ++k)
            slot[k] = okf ? cf[k] : (okd ? cd[k] : k);
        mism = 0;
    }
    __syncthreads();

    for (int k = 0; k < 3; ++k) {
        double v = use64 ? ((const double*)bufs[k])[c]
                         : (double)((const float*)bufs[k])[c];
        g_c[slot[k]][c] = v;
    }
    __syncthreads();

    const double PI = 3.14159265358979323846;
    double lmin = log(2.0 * PI * 10.0  / 24000.0);
    double lmax = log(2.0 * PI * 100.0 / 24000.0);
    double th = exp(lmin + (double)c * ((lmax - lmin) / 63.0));
    double r  = 0.9999 + (double)c * ((0.99999 - 0.9999) / 63.0);
    if (c == 63) { th = 2.0 * PI * 100.0 / 24000.0; r = 0.99999; }
    double ra1 = -2.0 * r * cos(th);
    double ra2 = r * r;
    double rb0 = (1.0 - r) * 0.5;

    if (fabs(ra1 - g_c[0][c]) > 1e-5 ||
        fabs(ra2 - g_c[1][c]) > 1e-5 ||
        fabs(rb0 - g_c[2][c]) > 1e-8)
        atomicOr(&mism, 1);
    __syncthreads();

    if (!mism) {
        g_c[0][c] = ra1;
        g_c[1][c] = ra2;
        g_c[2][c] = rb0;
    }
}

// ---------------------------------------------------------------------------
// Fused kernel. Blocks 0..7: psi segments + A. Blocks 8..: fp32 recurrence.
// ---------------------------------------------------------------------------
__global__ void __launch_bounds__(64) kphi_pass1(
    const float* __restrict__ pred, const float* __restrict__ targ)
{
    __shared__ float xs[LCH];
    int c = threadIdx.x;

    if (blockIdx.x < 8) {
        int seg = blockIdx.x;
        double m00 = -g_c[0][c], m01 = -g_c[1][c];

        double p00 = 1, p01 = 0, p10 = 0, p11 = 1;
        double b00 = m00, b01 = m01, b10 = 1.0, b11 = 0.0;
        int e = seg * 125;
        while (e) {
            if (e & 1) {
                double t00 = p00 * b00 + p01 * b10, t01 = p00 * b01 + p01 * b11;
                double t10 = p10 * b00 + p11 * b10, t11 = p10 * b01 + p11 * b11;
                p00 = t00; p01 = t01; p10 = t10; p11 = t11;
            }
            e >>= 1;
            if (e) {
                double t00 = b00 * b00 + b01 * b10, t01 = b00 * b01 + b01 * b11;
                double t10 = b10 * b00 + b11 * b10, t11 = b10 * b01 + b11 * b11;
                b00 = t00; b01 = t01; b10 = t10; b11 = t11;
            }
        }
        double u1 = p00, u2 = p10, v1 = p01, v2 = p11;
        int j0 = seg * 125;
        for (int j = j0; j < j0 + 125; ++j) {
            double yu = fma(m00, u1, m01 * u2);
            double yv = fma(m00, v1, m01 * v2);
            g_psi[j][c][0] = (float)(yu + yv);
            g_psi[j][c][1] = (float)yv;
            if (seg == 7) {
                if (j == LCH - 2) { g_A[c][2] = yu; g_A[c][3] = yv; }
                if (j == LCH - 1) { g_A[c][0] = yu; g_A[c][1] = yv; }
            }
            u2 = u1; u1 = yu;
            v2 = v1; v1 = yv;
        }
        return;
    }

    int idx = blockIdx.x - 8;
    int k = idx % NCHUNK;
    int s = idx / NCHUNK;
    int sig = s >> 3, b = (s >> 1) & 3, dir = s & 1;
    const float* x = (sig ? targ : pred) + b * TLEN;

    int k0 = k * LCH;
    if (dir == 0) {
        for (int j = c; j < LCH; j += 64) xs[j] = x[k0 + j];
    } else {
        for (int j = c; j < LCH; j += 64) xs[j] = x[TLEN - 1 - (k0 + j)];
    }
    __syncthreads();

    double a1d = -g_c[0][c], a2d = -g_c[1][c];
    float na1h = (float)a1d;  float na1l = (float)(a1d - (double)na1h);
    float na2h = (float)a2d;  float na2l = (float)(a2d - (double)na2h);
    float b0f  = (float)g_c[2][c];

    float y1 = 0.f, y2 = 0.f;
    if (k < CH0) {
        #pragma unroll 4
        for (int j = 0; j < LCH; ++j) {
            float t = fmaf(na2l, y2, fmaf(na1l, y1, b0f * xs[j]));
            float y = fmaf(na1h, y1, fmaf(na2h, y2, t));
            y2 = y1; y1 = y;
        }
    } else {
        __nv_bfloat16* yrow = g_Yh + (size_t)((sig * 4 + b) * TV) * 128
                                   + dir * 64 + c;
        int tl0 = dir ? (TLEN - 1 - MARGIN - k0) : (k0 - MARGIN);
        int tstep = dir ? -1 : 1;
        #pragma unroll 4
        for (int j = 0; j < LCH; ++j) {
            float t = fmaf(na2l, y2, fmaf(na1l, y1, b0f * xs[j]));
            float y = fmaf(na1h, y1, fmaf(na2h, y2, t));
            yrow[(size_t)(tl0 + j * tstep) * 128] = __float2bfloat16_rn(y);
            y2 = y1; y1 = y;
        }
    }
    g_E[s][k][c][0] = (double)y1;
    g_E[s][k][c][1] = (double)y2;
}

// ---------------------------------------------------------------------------
// Chunk-state propagation with batched prefetch. Writes fp32 (s1, s1-s2).
// ---------------------------------------------------------------------------
__global__ void __launch_bounds__(64) combine() {
    int s = blockIdx.x;
    int c = threadIdx.x;
    double A00 = g_A[c][0], A01 = g_A[c][1], A10 = g_A[c][2], A11 = g_A[c][3];
    double s1 = 0.0, s2 = 0.0;
    for (int kb = 0; kb < NCHUNK; kb += 8) {
        double e[8][2];
        #pragma unroll
        for (int i = 0; i < 8; ++i) {
            e[i][0] = g_E[s][kb + i][c][0];
            e[i][1] = g_E[s][kb + i][c][1];
        }
        #pragma unroll
        for (int i = 0; i < 8; ++i) {
            int k = kb + i;
            if (k >= CH0) {
                g_Sf[s][k - CH0][c][0] = (float)s1;
                g_Sf[s][k - CH0][c][1] = (float)(s1 - s2);
            }
            double n1 = fma(A00, s1, fma(A01, s2, e[i][0]));
            double n2 = fma(A10, s1, fma(A11, s2, e[i][1]));
            s1 = n1; s2 = n2;
        }
    }
}

// ---------------------------------------------------------------------------
// Stage B helpers
// ---------------------------------------------------------------------------
__device__ __forceinline__ float tanh_fast(float x) {
    float r;
    asm("tanh.approx.f32 %0, %1;" : "=f"(r) : "f"(x));
    return r;
}
__device__ __forceinline__ void ldsm4(unsigned& r0, unsigned& r1,
                                      unsigned& r2, unsigned& r3,
                                      unsigned addr) {
    asm volatile("ldmatrix.sync.aligned.m8n8.x4.shared.b16 {%0,%1,%2,%3}, [%4];"
                 : "=r"(r0), "=r"(r1), "=r"(r2), "=r"(r3) : "r"(addr));
}
__device__ __forceinline__ void mma16816(float* d, const unsigned* a,
                                         unsigned b0, unsigned b1) {
    asm volatile(
        "mma.sync.aligned.m16n8k16.row.col.f32.bf16.bf16.f32 "
        "{%0,%1,%2,%3}, {%4,%5,%6,%7}, {%8,%9}, {%0,%1,%2,%3};"
        : "+f"(d[0]), "+f"(d[1]), "+f"(d[2]), "+f"(d[3])
        : "r"(a[0]), "r"(a[1]), "r"(a[2]), "r"(a[3]), "r"(b0), "r"(b1));
}

// ---------------------------------------------------------------------------
// Stage B: 128 thr = 4 warps; warp w covers t = w*16..+15, full o=64,
// both signals. bf16 mma.sync, K = 128 in 8 steps.
// ---------------------------------------------------------------------------
__global__ void __launch_bounds__(128, 3) stageB(const float* __restrict__ W) {
    extern __shared__ char sm[];
    // layout: Wsh bf16[64o][136], then Vsh bf16[2 sig][64 t][136]
    int tid = threadIdx.x;
    int b   = blockIdx.y;
    int t0  = blockIdx.x * TT;

    // ---- stage W (bf16, [o][c] rows of 272B) ----
    const float2* Wf2 = (const float2*)W;
    for (int i = tid; i < 64 * 64; i += 128) {
        int o = i >> 6, c2 = i & 63;
        float2 wv = Wf2[o * 64 + c2];
        unsigned u;
        asm("cvt.rn.bf16x2.f32 %0, %1, %2;" : "=r"(u) : "f"(wv.y), "f"(wv.x));
        *(unsigned*)(sm + o * ROWB + c2 * 4) = u;
    }

    // ---- stage V with correction-by-recurrence ----
    {
        int sid = tid >> 6;              // 0 = pred, 1 = target
        int cp  = tid & 63;              // c-pair index: c = 2cp, 2cp+1
        int dir = cp >> 5;               // uniform per warp
        int cA  = (2 * cp) & 63;
        int sp  = sid * 8 + b * 2 + dir;

        float na1A = (float)(-g_c[0][cA]),     na2A = (float)(-g_c[1][cA]);
        float na1B = (float)(-g_c[0][cA + 1]), na2B = (float)(-g_c[1][cA + 1]);

        const unsigned* Yrow = (const unsigned*)g_Yh
                             + ((size_t)(sid * 4 + b) * TV + t0) * 64 + cp;
        unsigned* vout = (unsigned*)(sm + WBYTES + sid * VSIGB) + cp;

        if (dir == 0) {
            int step = 40000 + t0;
            int kk = step / 1000;
            int j  = step - kk * 1000;
            kk -= 40;
            float4 S = *(const float4*)&g_Sf[sp][kk][cA][0];
            float h1A = 0, h2A = 0, h1B = 0, h2B = 0;
            if (j > 0) {
                float4 pm1 = *(const float4*)&g_psi[j - 1][cA][0];
                float4 pm2 = (j >= 2) ? *(const float4*)&g_psi[j - 2][cA][0]
                                      : make_float4(1.f, 0.f, 1.f, 0.f);
                h1A = pm1.x * S.x - pm1.y * S.y;
                h1B = pm1.z * S.z - pm1.w * S.w;
                h2A = pm2.x * S.x - pm2.y * S.y;
                h2B = pm2.z * S.z - pm2.w * S.w;
            }
            for (int tt = 0; tt < TT; ++tt) {
                if (j == 0) {
                    S = *(const float4*)&g_Sf[sp][kk][cA][0];
                    h1A = S.x; h2A = S.x - S.y;
                    h1B = S.z; h2B = S.z - S.w;
                }
                float hA = fmaf(na1A, h1A, na2A * h2A);
                float hB = fmaf(na1B, h1B, na2B * h2B);
                unsigned u = Yrow[(size_t)tt * 64];
                float vA = __uint_as_float(u << 16) + hA;
                float vB = __uint_as_float(u & 0xffff0000u) + hB;
                unsigned o;
                asm("cvt.rn.bf16x2.f32 %0, %1, %2;" : "=r"(o)
                    : "f"(vB), "f"(vA));
                vout[tt * (ROWB / 4)] = o;
                h2A = h1A; h1A = hA;
                h2B = h1B; h1B = hB;
                if (++j == 1000) { j = 0; ++kk; }
            }
        } else {
            int step = 79999 - t0;
            int kk = step / 1000;
            int j  = step - kk * 1000;
            kk -= 40;
            float A1A = (float)g_c[0][cA],     A1B = (float)g_c[0][cA + 1];
            float ivA = (float)(-1.0 / g_c[1][cA]);
            float ivB = (float)(-1.0 / g_c[1][cA + 1]);
            float4 p8 = *(const float4*)&g_psi[998][cA][0];
            float4 p9 = *(const float4*)&g_psi[999][cA][0];
            float4 S  = *(const float4*)&g_Sf[sp][kk][cA][0];
            float hcA, hnA, hcB, hnB;
            if (j <= 998) {
                float4 pj  = *(const float4*)&g_psi[j][cA][0];
                float4 pj1 = *(const float4*)&g_psi[j + 1][cA][0];
                hcA = pj.x * S.x - pj.y * S.y;
                hcB = pj.z * S.z - pj.w * S.w;
                hnA = pj1.x * S.x - pj1.y * S.y;
                hnB = pj1.z * S.z - pj1.w * S.w;
            } else {
                hcA = p9.x * S.x - p9.y * S.y;
                hcB = p9.z * S.z - p9.w * S.w;
                float h8A = p8.x * S.x - p8.y * S.y;
                float h8B = p8.z * S.z - p8.w * S.w;
                hnA = fmaf(na1A, hcA, na2A * h8A);   // h[1000]
                hnB = fmaf(na1B, hcB, na2B * h8B);
            }
            bool rel = false;
            for (int tt = 0; tt < TT; ++tt) {
                if (rel) {
                    S = *(const float4*)&g_Sf[sp][kk][cA][0];
                    hcA = p9.x * S.x - p9.y * S.y;
                    hcB = p9.z * S.z - p9.w * S.w;
                    float h8A = p8.x * S.x - p8.y * S.y;
                    float h8B = p8.z * S.z - p8.w * S.w;
                    hnA = fmaf(na1A, hcA, na2A * h8A);
                    hnB = fmaf(na1B, hcB, na2B * h8B);
                    rel = false;
                }
                unsigned u = Yrow[(size_t)tt * 64];
                float vA = __uint_as_float(u << 16) + hcA;
                float vB = __uint_as_float(u & 0xffff0000u) + hcB;
                unsigned o;
                asm("cvt.rn.bf16x2.f32 %0, %1, %2;" : "=r"(o)
                    : "f"(vB), "f"(vA));
                vout[tt * (ROWB / 4)] = o;
                float hwA = ivA * fmaf(A1A, hcA, hnA);   // h[j-1]
                float hwB = ivB * fmaf(A1B, hcB, hnB);
                hnA = hcA; hcA = hwA;
                hnB = hcB; hcB = hwB;
                if (--j < 0) { j = 999; --kk; rel = true; }
            }
        }
    }
    __syncthreads();

    // ---- tensor-core GEMM ----
    int w = tid >> 5, lane = tid & 31;
    int tw = w * 16;
    unsigned sb = (unsigned)__cvta_generic_to_shared(sm);
    unsigned a_base = sb + (unsigned)(lane & 15) * ROWB
                         + ((lane & 16) ? 16u : 0u);
    unsigned b_base = sb + WBYTES
                    + (unsigned)(tw + (lane & 7) + ((lane & 16) ? 8 : 0)) * ROWB
                    + ((lane & 8) ? 16u : 0u);

    float acc[2][4][2][4];
    #pragma unroll
    for (int s2 = 0; s2 < 2; ++s2)
        #pragma unroll
        for (int m = 0; m < 4; ++m)
            #pragma unroll
            for (int n = 0; n < 2; ++n)
                #pragma unroll
                for (int i = 0; i < 4; ++i) acc[s2][m][n][i] = 0.f;

    #pragma unroll
    for (int k = 0; k < 8; ++k) {
        unsigned a[4][4];
        #pragma unroll
        for (int m = 0; m < 4; ++m)
            ldsm4(a[m][0], a[m][1], a[m][2], a[m][3],
                  a_base + (unsigned)m * (16 * ROWB) + (unsigned)k * 32);
        #pragma unroll
        for (int s2 = 0; s2 < 2; ++s2) {
            unsigned r0, r1, r2, r3;
            ldsm4(r0, r1, r2, r3,
                  b_base + (unsigned)s2 * VSIGB + (unsigned)k * 32);
            #pragma unroll
            for (int m = 0; m < 4; ++m) {
                mma16816(acc[s2][m][0], a[m], r0, r1);
                mma16816(acc[s2][m][1], a[m], r2, r3);
            }
        }
    }

    // ---- epilogue: |tanh(p) - tanh(t)| ----
    float lsum = 0.f;
    #pragma unroll
    for (int m = 0; m < 4; ++m)
        #pragma unroll
        for (int n = 0; n < 2; ++n)
            #pragma unroll
            for (int i = 0; i < 4; ++i)
                lsum += fabsf(tanh_fast(acc[0][m][n][i])
                            - tanh_fast(acc[1][m][n][i]));

    #pragma unroll
    for (int off = 16; off; off >>= 1)
        lsum += __shfl_xor_sync(0xffffffffu, lsum, off);

    __shared__ float red[4];
    if (lane == 0) red[w] = lsum;
    __syncthreads();
    if (tid == 0)
        g_part[b * NTB + blockIdx.x] =
            (double)((red[0] + red[1]) + (red[2] + red[3]));
}

// ---------------------------------------------------------------------------
// Deterministic final reduction -> mean
// ---------------------------------------------------------------------------
__global__ void __launch_bounds__(256) finalize(float* out) {
    __shared__ double sd[256];
    double acc = 0.0;
    for (int i = threadIdx.x; i < NPART; i += 256) acc += g_part[i];
    sd[threadIdx.x] = acc;
    __syncthreads();
    for (int s = 128; s > 0; s >>= 1) {
        if (threadIdx.x < s) sd[threadIdx.x] += sd[threadIdx.x + s];
        __syncthreads();
    }
    if (threadIdx.x == 0)
        out[0] = (float)(sd[0] / (4.0 * 64.0 * 40000.0));
}

// ---------------------------------------------------------------------------
extern "C" void kernel_launch(void* const* d_in, const int* in_sizes, int n_in,
                              void* d_out, int out_size) {
    const float *pred = 0, *targ = 0, *W = 0;
    const void  *cf[3] = { 0, 0, 0 };
    int nBig = 0, nSmall = 0;
    for (int i = 0; i < n_in; ++i) {
        int sz = in_sizes[i];
        if (sz == 480000) {
            if (nBig == 0) pred = (const float*)d_in[i];
            else           targ = (const float*)d_in[i];
            ++nBig;
        } else if (sz == 64 && nSmall < 3) {
            cf[nSmall++] = d_in[i];
        } else if (sz == 8192) {
            W = (const float*)d_in[i];
        }
    }
    float* out = (float*)d_out;

    cudaFuncSetAttribute(stageB, cudaFuncAttributeMaxDynamicSharedMemorySize,
                         SMEM_B);

    prep<<<1, 64>>>(cf[0], cf[1], cf[2]);
    kphi_pass1<<<8 + NCHUNK * NSEQ, 64>>>(pred, targ);
    combine<<<NSEQ, 64>>>();
    stageB<<<dim3(NTB, 4), 128, SMEM_B>>>(W);
    finalize<<<1, 256>>>(out);
}

// round 11
// speedup vs baseline: 10.7264x; 1.3806x over previous
#include <cuda_runtime.h>
#include <cuda_bf16.h>
#include <math.h>

// ---------------------------------------------------------------------------
// ESpaceLoss: biquad filter bank fwd+bwd -> tanh(W x) -> mean |p - t|
//
//   prep      : value-classified, dtype-robust coefficient load + analytic
//               fp64 reconstruction (validated against provided buffers)
//   kphi_pass1: fused. Blocks 0..7: psi tables + chunk transition A.
//               Blocks 8..: fp32 recurrence (double-float coeffs), stores
//               valid-region y as bf16 + end states E.
//   combine   : sequential 2x2 fp64 state propagation -> g_Sf (fp32)
//   stageB    : phase A: wide coalesced gmem->smem copy of the bf16 Y tile;
//               phase B: homogeneous correction as smem RMW driven by a
//               per-row 2-FMA recurrence; then bf16 mma.sync GEMM for both
//               signals; tanh.approx + |diff| sum.
//   finalize  : deterministic reduction -> scalar mean
// ---------------------------------------------------------------------------

#define TLEN   120000
#define LCH    1000
#define NCHUNK 80
#define CH0    40
#define NCHV   40
#define MARGIN 40000
#define TV     40000
#define NC     64
#define NSEQ   16
#define TT     64          // stage B t-tile
#define NTB    (TV / TT)   // 625
#define NPART  (NTB * 4)   // 2500

#define ROWB   272                     // bf16 tile row stride in bytes (17 lines)
#define WBYTES (64 * ROWB)             // 17408
#define VSIGB  (64 * ROWB)             // 17408 per signal
#define SMEM_B (WBYTES + 2 * VSIGB)    // 52224

__device__ double g_c[3][NC];                  // a1, a2, b0 (normalized fp64)
__device__ double g_A[NC][4];                  // chunk transition M^L
__device__ double g_E[NSEQ][NCHUNK][NC][2];    // particular end states
__device__ float  g_Sf[NSEQ][NCHV][NC][2];     // (s1, s1-s2) per valid chunk
__device__ float  g_psi[LCH][NC][2];           // homogeneous basis (psi1, psi2)
__device__ __nv_bfloat16 g_Yh[(size_t)2 * 4 * TV * 128]; // [sig][b][t][dir*64+c]
__device__ double g_part[NPART];

// ---------------------------------------------------------------------------
// Coefficient prep (dtype/order robust, validated analytic reconstruction)
// ---------------------------------------------------------------------------
__device__ __forceinline__ int coeff_class(double v) {
    if (!isfinite(v)) return -1;
    if (v > -2.5 && v < -1.5) return 0;       // a1
    if (v >  0.5 && v <  1.5) return 1;       // a2
    if (v > 1e-7 && v < 1e-2) return 2;       // b0
    return -1;
}

__global__ void __launch_bounds__(64) prep(const void* p0, const void* p1,
                                           const void* p2) {
    const void* bufs[3] = { p0, p1, p2 };
    int c = threadIdx.x;
    __shared__ int slot[3];
    __shared__ int use64;
    __shared__ int mism;

    if (c == 0) {
        int cf[3], cd[3];
        for (int k = 0; k < 3; ++k) {
            cf[k] = coeff_class((double)((const float*)bufs[k])[0]);
            cd[k] = coeff_class(((const double*)bufs[k])[0]);
        }
        bool okf = cf[0] >= 0 && cf[1] >= 0 && cf[2] >= 0 &&
                   cf[0] != cf[1] && cf[0] != cf[2] && cf[1] != cf[2];
        bool okd = cd[0] >= 0 && cd[1] >= 0 && cd[2] >= 0 &&
                   cd[0] != cd[1] && cd[0] != cd[2] && cd[1] != cd[2];
        use64 = okf ? 0 : 1;
        for (int k = 0; k < 3; ++k)
            slot[k] = okf ? cf[k] : (okd ? cd[k] : k);
        mism = 0;
    }
    __syncthreads();

    for (int k = 0; k < 3; ++k) {
        double v = use64 ? ((const double*)bufs[k])[c]
                         : (double)((const float*)bufs[k])[c];
        g_c[slot[k]][c] = v;
    }
    __syncthreads();

    const double PI = 3.14159265358979323846;
    double lmin = log(2.0 * PI * 10.0  / 24000.0);
    double lmax = log(2.0 * PI * 100.0 / 24000.0);
    double th = exp(lmin + (double)c * ((lmax - lmin) / 63.0));
    double r  = 0.9999 + (double)c * ((0.99999 - 0.9999) / 63.0);
    if (c == 63) { th = 2.0 * PI * 100.0 / 24000.0; r = 0.99999; }
    double ra1 = -2.0 * r * cos(th);
    double ra2 = r * r;
    double rb0 = (1.0 - r) * 0.5;

    if (fabs(ra1 - g_c[0][c]) > 1e-5 ||
        fabs(ra2 - g_c[1][c]) > 1e-5 ||
        fabs(rb0 - g_c[2][c]) > 1e-8)
        atomicOr(&mism, 1);
    __syncthreads();

    if (!mism) {
        g_c[0][c] = ra1;
        g_c[1][c] = ra2;
        g_c[2][c] = rb0;
    }
}

// ---------------------------------------------------------------------------
// Fused kernel. Blocks 0..7: psi segments + A. Blocks 8..: fp32 recurrence.
// ---------------------------------------------------------------------------
__global__ void __launch_bounds__(64) kphi_pass1(
    const float* __restrict__ pred, const float* __restrict__ targ)
{
    __shared__ float xs[LCH];
    int c = threadIdx.x;

    if (blockIdx.x < 8) {
        int seg = blockIdx.x;
        double m00 = -g_c[0][c], m01 = -g_c[1][c];

        double p00 = 1, p01 = 0, p10 = 0, p11 = 1;
        double b00 = m00, b01 = m01, b10 = 1.0, b11 = 0.0;
        int e = seg * 125;
        while (e) {
            if (e & 1) {
                double t00 = p00 * b00 + p01 * b10, t01 = p00 * b01 + p01 * b11;
                double t10 = p10 * b00 + p11 * b10, t11 = p10 * b01 + p11 * b11;
                p00 = t00; p01 = t01; p10 = t10; p11 = t11;
            }
            e >>= 1;
            if (e) {
                double t00 = b00 * b00 + b01 * b10, t01 = b00 * b01 + b01 * b11;
                double t10 = b10 * b00 + b11 * b10, t11 = b10 * b01 + b11 * b11;
                b00 = t00; b01 = t01; b10 = t10; b11 = t11;
            }
        }
        double u1 = p00, u2 = p10, v1 = p01, v2 = p11;
        int j0 = seg * 125;
        for (int j = j0; j < j0 + 125; ++j) {
            double yu = fma(m00, u1, m01 * u2);
            double yv = fma(m00, v1, m01 * v2);
            g_psi[j][c][0] = (float)(yu + yv);
            g_psi[j][c][1] = (float)yv;
            if (seg == 7) {
                if (j == LCH - 2) { g_A[c][2] = yu; g_A[c][3] = yv; }
                if (j == LCH - 1) { g_A[c][0] = yu; g_A[c][1] = yv; }
            }
            u2 = u1; u1 = yu;
            v2 = v1; v1 = yv;
        }
        return;
    }

    int idx = blockIdx.x - 8;
    int k = idx % NCHUNK;
    int s = idx / NCHUNK;
    int sig = s >> 3, b = (s >> 1) & 3, dir = s & 1;
    const float* x = (sig ? targ : pred) + b * TLEN;

    int k0 = k * LCH;
    if (dir == 0) {
        for (int j = c; j < LCH; j += 64) xs[j] = x[k0 + j];
    } else {
        for (int j = c; j < LCH; j += 64) xs[j] = x[TLEN - 1 - (k0 + j)];
    }
    __syncthreads();

    double a1d = -g_c[0][c], a2d = -g_c[1][c];
    float na1h = (float)a1d;  float na1l = (float)(a1d - (double)na1h);
    float na2h = (float)a2d;  float na2l = (float)(a2d - (double)na2h);
    float b0f  = (float)g_c[2][c];

    float y1 = 0.f, y2 = 0.f;
    if (k < CH0) {
        #pragma unroll 4
        for (int j = 0; j < LCH; ++j) {
            float t = fmaf(na2l, y2, fmaf(na1l, y1, b0f * xs[j]));
            float y = fmaf(na1h, y1, fmaf(na2h, y2, t));
            y2 = y1; y1 = y;
        }
    } else {
        __nv_bfloat16* yrow = g_Yh + (size_t)((sig * 4 + b) * TV) * 128
                                   + dir * 64 + c;
        int tl0 = dir ? (TLEN - 1 - MARGIN - k0) : (k0 - MARGIN);
        int tstep = dir ? -1 : 1;
        #pragma unroll 4
        for (int j = 0; j < LCH; ++j) {
            float t = fmaf(na2l, y2, fmaf(na1l, y1, b0f * xs[j]));
            float y = fmaf(na1h, y1, fmaf(na2h, y2, t));
            yrow[(size_t)(tl0 + j * tstep) * 128] = __float2bfloat16_rn(y);
            y2 = y1; y1 = y;
        }
    }
    g_E[s][k][c][0] = (double)y1;
    g_E[s][k][c][1] = (double)y2;
}

// ---------------------------------------------------------------------------
// Chunk-state propagation with batched prefetch. Writes fp32 (s1, s1-s2).
// ---------------------------------------------------------------------------
__global__ void __launch_bounds__(64) combine() {
    int s = blockIdx.x;
    int c = threadIdx.x;
    double A00 = g_A[c][0], A01 = g_A[c][1], A10 = g_A[c][2], A11 = g_A[c][3];
    double s1 = 0.0, s2 = 0.0;
    for (int kb = 0; kb < NCHUNK; kb += 8) {
        double e[8][2];
        #pragma unroll
        for (int i = 0; i < 8; ++i) {
            e[i][0] = g_E[s][kb + i][c][0];
            e[i][1] = g_E[s][kb + i][c][1];
        }
        #pragma unroll
        for (int i = 0; i < 8; ++i) {
            int k = kb + i;
            if (k >= CH0) {
                g_Sf[s][k - CH0][c][0] = (float)s1;
                g_Sf[s][k - CH0][c][1] = (float)(s1 - s2);
            }
            double n1 = fma(A00, s1, fma(A01, s2, e[i][0]));
            double n2 = fma(A10, s1, fma(A11, s2, e[i][1]));
            s1 = n1; s2 = n2;
        }
    }
}

// ---------------------------------------------------------------------------
// Stage B helpers
// ---------------------------------------------------------------------------
__device__ __forceinline__ float tanh_fast(float x) {
    float r;
    asm("tanh.approx.f32 %0, %1;" : "=f"(r) : "f"(x));
    return r;
}
__device__ __forceinline__ void ldsm4(unsigned& r0, unsigned& r1,
                                      unsigned& r2, unsigned& r3,
                                      unsigned addr) {
    asm volatile("ldmatrix.sync.aligned.m8n8.x4.shared.b16 {%0,%1,%2,%3}, [%4];"
                 : "=r"(r0), "=r"(r1), "=r"(r2), "=r"(r3) : "r"(addr));
}
__device__ __forceinline__ void mma16816(float* d, const unsigned* a,
                                         unsigned b0, unsigned b1) {
    asm volatile(
        "mma.sync.aligned.m16n8k16.row.col.f32.bf16.bf16.f32 "
        "{%0,%1,%2,%3}, {%4,%5,%6,%7}, {%8,%9}, {%0,%1,%2,%3};"
        : "+f"(d[0]), "+f"(d[1]), "+f"(d[2]), "+f"(d[3])
        : "r"(a[0]), "r"(a[1]), "r"(a[2]), "r"(a[3]), "r"(b0), "r"(b1));
}

// ---------------------------------------------------------------------------
// Stage B: 128 thr = 4 warps; warp w covers t = w*16..+15, full o=64,
// both signals. bf16 mma.sync, K = 128 in 8 steps.
// ---------------------------------------------------------------------------
__global__ void __launch_bounds__(128, 3) stageB(const float* __restrict__ W) {
    extern __shared__ char sm[];
    // layout: Wsh bf16[64o][136], then Vsh bf16[2 sig][64 t][136]
    int tid = threadIdx.x;
    int b   = blockIdx.y;
    int t0  = blockIdx.x * TT;

    // ---- stage W (bf16, [o][c] rows of 272B) ----
    const float2* Wf2 = (const float2*)W;
    for (int i = tid; i < 64 * 64; i += 128) {
        int o = i >> 6, c2 = i & 63;
        float2 wv = Wf2[o * 64 + c2];
        unsigned u;
        asm("cvt.rn.bf16x2.f32 %0, %1, %2;" : "=r"(u) : "f"(wv.y), "f"(wv.x));
        *(unsigned*)(sm + o * ROWB + c2 * 4) = u;
    }

    // ---- phase A: raw Y tile gmem -> smem, wide coalesced (MLP=16) ----
    {
        const uint4* srcP = (const uint4*)(g_Yh + ((size_t)(0 * 4 + b) * TV + t0) * 128);
        const uint4* srcT = (const uint4*)(g_Yh + ((size_t)(1 * 4 + b) * TV + t0) * 128);
        #pragma unroll
        for (int it = 0; it < 16; ++it) {
            int idx = tid + it * 128;          // 0..2047
            int R = idx >> 4, col = idx & 15;  // R: 0..127 rows, col: 16B unit
            int sig = R >> 6, tt = R & 63;
            const uint4* src = sig ? srcT : srcP;
            uint4 v = src[tt * 16 + col];
            *(uint4*)(sm + WBYTES + sig * VSIGB + tt * ROWB + col * 16) = v;
        }
    }
    __syncthreads();

    // ---- phase B: homogeneous correction as smem RMW ----
    {
        int sid = tid >> 6;              // 0 = pred, 1 = target
        int cp  = tid & 63;              // c-pair index: c = 2cp, 2cp+1
        int dir = cp >> 5;               // uniform per warp
        int cA  = (2 * cp) & 63;
        int sp  = sid * 8 + b * 2 + dir;

        float na1A = (float)(-g_c[0][cA]),     na2A = (float)(-g_c[1][cA]);
        float na1B = (float)(-g_c[0][cA + 1]), na2B = (float)(-g_c[1][cA + 1]);

        unsigned* vword = (unsigned*)(sm + WBYTES + sid * VSIGB) + cp;

        if (dir == 0) {
            int step = 40000 + t0;
            int kk = step / 1000;
            int j  = step - kk * 1000;
            kk -= 40;
            float4 S = *(const float4*)&g_Sf[sp][kk][cA][0];
            float h1A = 0, h2A = 0, h1B = 0, h2B = 0;
            if (j > 0) {
                float4 pm1 = *(const float4*)&g_psi[j - 1][cA][0];
                float4 pm2 = (j >= 2) ? *(const float4*)&g_psi[j - 2][cA][0]
                                      : make_float4(1.f, 0.f, 1.f, 0.f);
                h1A = pm1.x * S.x - pm1.y * S.y;
                h1B = pm1.z * S.z - pm1.w * S.w;
                h2A = pm2.x * S.x - pm2.y * S.y;
                h2B = pm2.z * S.z - pm2.w * S.w;
            }
            for (int tt = 0; tt < TT; ++tt) {
                if (j == 0) {
                    S = *(const float4*)&g_Sf[sp][kk][cA][0];
                    h1A = S.x; h2A = S.x - S.y;
                    h1B = S.z; h2B = S.z - S.w;
                }
                float hA = fmaf(na1A, h1A, na2A * h2A);
                float hB = fmaf(na1B, h1B, na2B * h2B);
                unsigned u = vword[tt * (ROWB / 4)];
                float vA = __uint_as_float(u << 16) + hA;
                float vB = __uint_as_float(u & 0xffff0000u) + hB;
                unsigned o;
                asm("cvt.rn.bf16x2.f32 %0, %1, %2;" : "=r"(o)
                    : "f"(vB), "f"(vA));
                vword[tt * (ROWB / 4)] = o;
                h2A = h1A; h1A = hA;
                h2B = h1B; h1B = hB;
                if (++j == 1000) { j = 0; ++kk; }
            }
        } else {
            int step = 79999 - t0;
            int kk = step / 1000;
            int j  = step - kk * 1000;
            kk -= 40;
            float A1A = (float)g_c[0][cA],     A1B = (float)g_c[0][cA + 1];
            float ivA = (float)(-1.0 / g_c[1][cA]);
            float ivB = (float)(-1.0 / g_c[1][cA + 1]);
            float4 p8 = *(const float4*)&g_psi[998][cA][0];
            float4 p9 = *(const float4*)&g_psi[999][cA][0];
            float4 S  = *(const float4*)&g_Sf[sp][kk][cA][0];
            float hcA, hnA, hcB, hnB;
            if (j <= 998) {
                float4 pj  = *(const float4*)&g_psi[j][cA][0];
                float4 pj1 = *(const float4*)&g_psi[j + 1][cA][0];
                hcA = pj.x * S.x - pj.y * S.y;
                hcB = pj.z * S.z - pj.w * S.w;
                hnA = pj1.x * S.x - pj1.y * S.y;
                hnB = pj1.z * S.z - pj1.w * S.w;
            } else {
                hcA = p9.x * S.x - p9.y * S.y;
                hcB = p9.z * S.z - p9.w * S.w;
                float h8A = p8.x * S.x - p8.y * S.y;
                float h8B = p8.z * S.z - p8.w * S.w;
                hnA = fmaf(na1A, hcA, na2A * h8A);   // h[1000]
                hnB = fmaf(na1B, hcB, na2B * h8B);
            }
            bool rel = false;
            for (int tt = 0; tt < TT; ++tt) {
                if (rel) {
                    S = *(const float4*)&g_Sf[sp][kk][cA][0];
                    hcA = p9.x * S.x - p9.y * S.y;
                    hcB = p9.z * S.z - p9.w * S.w;
                    float h8A = p8.x * S.x - p8.y * S.y;
                    float h8B = p8.z * S.z - p8.w * S.w;
                    hnA = fmaf(na1A, hcA, na2A * h8A);
                    hnB = fmaf(na1B, hcB, na2B * h8B);
                    rel = false;
                }
                unsigned u = vword[tt * (ROWB / 4)];
                float vA = __uint_as_float(u << 16) + hcA;
                float vB = __uint_as_float(u & 0xffff0000u) + hcB;
                unsigned o;
                asm("cvt.rn.bf16x2.f32 %0, %1, %2;" : "=r"(o)
                    : "f"(vB), "f"(vA));
                vword[tt * (ROWB / 4)] = o;
                float hwA = ivA * fmaf(A1A, hcA, hnA);   // h[j-1]
                float hwB = ivB * fmaf(A1B, hcB, hnB);
                hnA = hcA; hcA = hwA;
                hnB = hcB; hcB = hwB;
                if (--j < 0) { j = 999; --kk; rel = true; }
            }
        }
    }
    __syncthreads();

    // ---- tensor-core GEMM ----
    int w = tid >> 5, lane = tid & 31;
    int tw = w * 16;
    unsigned sb = (unsigned)__cvta_generic_to_shared(sm);
    unsigned a_base = sb + (unsigned)(lane & 15) * ROWB
                         + ((lane & 16) ? 16u : 0u);
    unsigned b_base = sb + WBYTES
                    + (unsigned)(tw + (lane & 7) + ((lane & 16) ? 8 : 0)) * ROWB
                    + ((lane & 8) ? 16u : 0u);

    float acc[2][4][2][4];
    #pragma unroll
    for (int s2 = 0; s2 < 2; ++s2)
        #pragma unroll
        for (int m = 0; m < 4; ++m)
            #pragma unroll
            for (int n = 0; n < 2; ++n)
                #pragma unroll
                for (int i = 0; i < 4; ++i) acc[s2][m][n][i] = 0.f;

    #pragma unroll
    for (int k = 0; k < 8; ++k) {
        unsigned a[4][4];
        #pragma unroll
        for (int m = 0; m < 4; ++m)
            ldsm4(a[m][0], a[m][1], a[m][2], a[m][3],
                  a_base + (unsigned)m * (16 * ROWB) + (unsigned)k * 32);
        #pragma unroll
        for (int s2 = 0; s2 < 2; ++s2) {
            unsigned r0, r1, r2, r3;
            ldsm4(r0, r1, r2, r3,
                  b_base + (unsigned)s2 * VSIGB + (unsigned)k * 32);
            #pragma unroll
            for (int m = 0; m < 4; ++m) {
                mma16816(acc[s2][m][0], a[m], r0, r1);
                mma16816(acc[s2][m][1], a[m], r2, r3);
            }
        }
    }

    // ---- epilogue: |tanh(p) - tanh(t)| ----
    float lsum = 0.f;
    #pragma unroll
    for (int m = 0; m < 4; ++m)
        #pragma unroll
        for (int n = 0; n < 2; ++n)
            #pragma unroll
            for (int i = 0; i < 4; ++i)
                lsum += fabsf(tanh_fast(acc[0][m][n][i])
                            - tanh_fast(acc[1][m][n][i]));

    #pragma unroll
    for (int off = 16; off; off >>= 1)
        lsum += __shfl_xor_sync(0xffffffffu, lsum, off);

    __shared__ float red[4];
    if (lane == 0) red[w] = lsum;
    __syncthreads();
    if (tid == 0)
        g_part[b * NTB + blockIdx.x] =
            (double)((red[0] + red[1]) + (red[2] + red[3]));
}

// ---------------------------------------------------------------------------
// Deterministic final reduction -> mean
// ---------------------------------------------------------------------------
__global__ void __launch_bounds__(256) finalize(float* out) {
    __shared__ double sd[256];
    double acc = 0.0;
    for (int i = threadIdx.x; i < NPART; i += 256) acc += g_part[i];
    sd[threadIdx.x] = acc;
    __syncthreads();
    for (int s = 128; s > 0; s >>= 1) {
        if (threadIdx.x < s) sd[threadIdx.x] += sd[threadIdx.x + s];
        __syncthreads();
    }
    if (threadIdx.x == 0)
        out[0] = (float)(sd[0] / (4.0 * 64.0 * 40000.0));
}

// ---------------------------------------------------------------------------
extern "C" void kernel_launch(void* const* d_in, const int* in_sizes, int n_in,
                              void* d_out, int out_size) {
    const float *pred = 0, *targ = 0, *W = 0;
    const void  *cf[3] = { 0, 0, 0 };
    int nBig = 0, nSmall = 0;
    for (int i = 0; i < n_in; ++i) {
        int sz = in_sizes[i];
        if (sz == 480000) {
            if (nBig == 0) pred = (const float*)d_in[i];
            else           targ = (const float*)d_in[i];
            ++nBig;
        } else if (sz == 64 && nSmall < 3) {
            cf[nSmall++] = d_in[i];
        } else if (sz == 8192) {
            W = (const float*)d_in[i];
        }
    }
    float* out = (float*)d_out;

    cudaFuncSetAttribute(stageB, cudaFuncAttributeMaxDynamicSharedMemorySize,
                         SMEM_B);

    prep<<<1, 64>>>(cf[0], cf[1], cf[2]);
    kphi_pass1<<<8 + NCHUNK * NSEQ, 64>>>(pred, targ);
    combine<<<NSEQ, 64>>>();
    stageB<<<dim3(NTB, 4), 128, SMEM_B>>>(W);
    finalize<<<1, 256>>>(out);
}

// round 12
// speedup vs baseline: 11.2161x; 1.0457x over previous
#include <cuda_runtime.h>
#include <cuda_bf16.h>
#include <math.h>

// ---------------------------------------------------------------------------
// ESpaceLoss: biquad filter bank fwd+bwd -> tanh(W x) -> mean |p - t|
//
//   prep      : value-classified, dtype-robust coefficient load + analytic
//               fp64 reconstruction; packs W to bf16 (g_Wh).
//   kphi_pass1: fused. Blocks 0..7: psi tables + chunk transition A.
//               Blocks 8..: fp32 recurrence, 2 channels/thread (1 warp = 1
//               (seq,chunk) task), packed STG.32 bf16 y + end states E.
//   combine   : sequential 2x2 fp64 state propagation -> g_Sf (fp32)
//   stageB    : cp.async staging of W/Y tiles; homogeneous correction by
//               DIRECT psi-table evaluation (independent per-t); bf16
//               mma.sync GEMM for both signals; tanh.approx + |diff| sum.
//   finalize  : deterministic reduction -> scalar mean
// ---------------------------------------------------------------------------

#define TLEN   120000
#define LCH    1000
#define NCHUNK 80
#define CH0    40
#define NCHV   40
#define MARGIN 40000
#define TV     40000
#define NC     64
#define NSEQ   16
#define TT     64          // stage B t-tile
#define NTB    (TV / TT)   // 625
#define NPART  (NTB * 4)   // 2500

#define ROWB   272                     // bf16 tile row stride in bytes (17 lines)
#define WBYTES (64 * ROWB)             // 17408
#define VSIGB  (64 * ROWB)             // 17408 per signal
#define SMEM_B (WBYTES + 2 * VSIGB)    // 52224

__device__ double g_c[3][NC];                  // a1, a2, b0 (normalized fp64)
__device__ double g_A[NC][4];                  // chunk transition M^L
__device__ double g_E[NSEQ][NCHUNK][NC][2];    // particular end states
__device__ float  g_Sf[NSEQ][NCHV][NC][2];     // (s1, s1-s2) per valid chunk
__device__ float  g_psi[LCH][NC][2];           // homogeneous basis (psi1, psi2)
__device__ unsigned g_Wh[4096];                // W as bf16x2, [o][c-pair]
__device__ __nv_bfloat16 g_Yh[(size_t)2 * 4 * TV * 128]; // [sig][b][t][dir*64+c]
__device__ double g_part[NPART];

// ---------------------------------------------------------------------------
// Coefficient prep (dtype/order robust, validated analytic reconstruction)
// + W -> bf16 packing.
// ---------------------------------------------------------------------------
__device__ __forceinline__ int coeff_class(double v) {
    if (!isfinite(v)) return -1;
    if (v > -2.5 && v < -1.5) return 0;       // a1
    if (v >  0.5 && v <  1.5) return 1;       // a2
    if (v > 1e-7 && v < 1e-2) return 2;       // b0
    return -1;
}

__global__ void __launch_bounds__(64) prep(const void* p0, const void* p1,
                                           const void* p2,
                                           const float* __restrict__ W) {
    const void* bufs[3] = { p0, p1, p2 };
    int c = threadIdx.x;
    __shared__ int slot[3];
    __shared__ int use64;
    __shared__ int mism;

    if (c == 0) {
        int cf[3], cd[3];
        for (int k = 0; k < 3; ++k) {
            cf[k] = coeff_class((double)((const float*)bufs[k])[0]);
            cd[k] = coeff_class(((const double*)bufs[k])[0]);
        }
        bool okf = cf[0] >= 0 && cf[1] >= 0 && cf[2] >= 0 &&
                   cf[0] != cf[1] && cf[0] != cf[2] && cf[1] != cf[2];
        bool okd = cd[0] >= 0 && cd[1] >= 0 && cd[2] >= 0 &&
                   cd[0] != cd[1] && cd[0] != cd[2] && cd[1] != cd[2];
        use64 = okf ? 0 : 1;
        for (int k = 0; k < 3; ++k)
            slot[k] = okf ? cf[k] : (okd ? cd[k] : k);
        mism = 0;
    }
    __syncthreads();

    for (int k = 0; k < 3; ++k) {
        double v = use64 ? ((const double*)bufs[k])[c]
                         : (double)((const float*)bufs[k])[c];
        g_c[slot[k]][c] = v;
    }
    __syncthreads();

    const double PI = 3.14159265358979323846;
    double lmin = log(2.0 * PI * 10.0  / 24000.0);
    double lmax = log(2.0 * PI * 100.0 / 24000.0);
    double th = exp(lmin + (double)c * ((lmax - lmin) / 63.0));
    double r  = 0.9999 + (double)c * ((0.99999 - 0.9999) / 63.0);
    if (c == 63) { th = 2.0 * PI * 100.0 / 24000.0; r = 0.99999; }
    double ra1 = -2.0 * r * cos(th);
    double ra2 = r * r;
    double rb0 = (1.0 - r) * 0.5;

    if (fabs(ra1 - g_c[0][c]) > 1e-5 ||
        fabs(ra2 - g_c[1][c]) > 1e-5 ||
        fabs(rb0 - g_c[2][c]) > 1e-8)
        atomicOr(&mism, 1);
    __syncthreads();

    if (!mism) {
        g_c[0][c] = ra1;
        g_c[1][c] = ra2;
        g_c[2][c] = rb0;
    }

    // pack W -> bf16x2 (same linear pair order as stageB smem rows)
    const float2* Wf2 = (const float2*)W;
    for (int i = c; i < 4096; i += 64) {
        float2 wv = Wf2[i];
        unsigned u;
        asm("cvt.rn.bf16x2.f32 %0, %1, %2;" : "=r"(u) : "f"(wv.y), "f"(wv.x));
        g_Wh[i] = u;
    }
}

// ---------------------------------------------------------------------------
// Fused kernel. Blocks 0..7: psi segments + A.
// Blocks 8..: fp32 recurrence, warp = one (seq,chunk) task, 2 ch/thread.
// ---------------------------------------------------------------------------
__global__ void __launch_bounds__(64) kphi_pass1(
    const float* __restrict__ pred, const float* __restrict__ targ)
{
    __shared__ float xs2[2][LCH];
    int tid = threadIdx.x;

    if (blockIdx.x < 8) {
        int c = tid;
        int seg = blockIdx.x;
        double m00 = -g_c[0][c], m01 = -g_c[1][c];

        double p00 = 1, p01 = 0, p10 = 0, p11 = 1;
        double b00 = m00, b01 = m01, b10 = 1.0, b11 = 0.0;
        int e = seg * 125;
        while (e) {
            if (e & 1) {
                double t00 = p00 * b00 + p01 * b10, t01 = p00 * b01 + p01 * b11;
                double t10 = p10 * b00 + p11 * b10, t11 = p10 * b01 + p11 * b11;
                p00 = t00; p01 = t01; p10 = t10; p11 = t11;
            }
            e >>= 1;
            if (e) {
                double t00 = b00 * b00 + b01 * b10, t01 = b00 * b01 + b01 * b11;
                double t10 = b10 * b00 + b11 * b10, t11 = b10 * b01 + b11 * b11;
                b00 = t00; b01 = t01; b10 = t10; b11 = t11;
            }
        }
        double u1 = p00, u2 = p10, v1 = p01, v2 = p11;
        int j0 = seg * 125;
        for (int j = j0; j < j0 + 125; ++j) {
            double yu = fma(m00, u1, m01 * u2);
            double yv = fma(m00, v1, m01 * v2);
            g_psi[j][c][0] = (float)(yu + yv);
            g_psi[j][c][1] = (float)yv;
            if (seg == 7) {
                if (j == LCH - 2) { g_A[c][2] = yu; g_A[c][3] = yv; }
                if (j == LCH - 1) { g_A[c][0] = yu; g_A[c][1] = yv; }
            }
            u2 = u1; u1 = yu;
            v2 = v1; v1 = yv;
        }
        return;
    }

    int w = tid >> 5, l = tid & 31;
    int task = (blockIdx.x - 8) * 2 + w;     // 0..1279
    int k = task % NCHUNK;
    int s = task / NCHUNK;
    int sig = s >> 3, b = (s >> 1) & 3, dir = s & 1;
    const float* x = (sig ? targ : pred) + b * TLEN;
    float* xs = xs2[w];

    int k0 = k * LCH;
    if (dir == 0) {
        for (int j = l; j < LCH; j += 32) xs[j] = x[k0 + j];
    } else {
        for (int j = l; j < LCH; j += 32) xs[j] = x[TLEN - 1 - (k0 + j)];
    }
    __syncwarp();

    int c0 = 2 * l, c1 = 2 * l + 1;
    double a1A = -g_c[0][c0], a2A = -g_c[1][c0];
    double a1B = -g_c[0][c1], a2B = -g_c[1][c1];
    float n1Ah = (float)a1A, n1Al = (float)(a1A - (double)n1Ah);
    float n2Ah = (float)a2A, n2Al = (float)(a2A - (double)n2Ah);
    float n1Bh = (float)a1B, n1Bl = (float)(a1B - (double)n1Bh);
    float n2Bh = (float)a2B, n2Bl = (float)(a2B - (double)n2Bh);
    float b0A = (float)g_c[2][c0], b0B = (float)g_c[2][c1];

    float y1a = 0.f, y2a = 0.f, y1b = 0.f, y2b = 0.f;
    if (k < CH0) {
        #pragma unroll 4
        for (int j = 0; j < LCH; ++j) {
            float xj = xs[j];
            float ta = fmaf(n2Al, y2a, fmaf(n1Al, y1a, b0A * xj));
            float ya = fmaf(n1Ah, y1a, fmaf(n2Ah, y2a, ta));
            float tb = fmaf(n2Bl, y2b, fmaf(n1Bl, y1b, b0B * xj));
            float yb = fmaf(n1Bh, y1b, fmaf(n2Bh, y2b, tb));
            y2a = y1a; y1a = ya;
            y2b = y1b; y1b = yb;
        }
    } else {
        unsigned* yrow = (unsigned*)(g_Yh
            + (size_t)((sig * 4 + b) * TV) * 128 + dir * 64 + c0);
        int tl0 = dir ? (TLEN - 1 - MARGIN - k0) : (k0 - MARGIN);
        int tstep = dir ? -1 : 1;
        #pragma unroll 4
        for (int j = 0; j < LCH; ++j) {
            float xj = xs[j];
            float ta = fmaf(n2Al, y2a, fmaf(n1Al, y1a, b0A * xj));
            float ya = fmaf(n1Ah, y1a, fmaf(n2Ah, y2a, ta));
            float tb = fmaf(n2Bl, y2b, fmaf(n1Bl, y1b, b0B * xj));
            float yb = fmaf(n1Bh, y1b, fmaf(n2Bh, y2b, tb));
            unsigned o;
            asm("cvt.rn.bf16x2.f32 %0, %1, %2;" : "=r"(o) : "f"(yb), "f"(ya));
            yrow[(size_t)(tl0 + j * tstep) * 64] = o;
            y2a = y1a; y1a = ya;
            y2b = y1b; y1b = yb;
        }
    }
    g_E[s][k][c0][0] = (double)y1a;
    g_E[s][k][c0][1] = (double)y2a;
    g_E[s][k][c1][0] = (double)y1b;
    g_E[s][k][c1][1] = (double)y2b;
}

// ---------------------------------------------------------------------------
// Chunk-state propagation with batched prefetch. Writes fp32 (s1, s1-s2).
// ---------------------------------------------------------------------------
__global__ void __launch_bounds__(64) combine() {
    int s = blockIdx.x;
    int c = threadIdx.x;
    double A00 = g_A[c][0], A01 = g_A[c][1], A10 = g_A[c][2], A11 = g_A[c][3];
    double s1 = 0.0, s2 = 0.0;
    for (int kb = 0; kb < NCHUNK; kb += 8) {
        double e[8][2];
        #pragma unroll
        for (int i = 0; i < 8; ++i) {
            e[i][0] = g_E[s][kb + i][c][0];
            e[i][1] = g_E[s][kb + i][c][1];
        }
        #pragma unroll
        for (int i = 0; i < 8; ++i) {
            int k = kb + i;
            if (k >= CH0) {
                g_Sf[s][k - CH0][c][0] = (float)s1;
                g_Sf[s][k - CH0][c][1] = (float)(s1 - s2);
            }
            double n1 = fma(A00, s1, fma(A01, s2, e[i][0]));
            double n2 = fma(A10, s1, fma(A11, s2, e[i][1]));
            s1 = n1; s2 = n2;
        }
    }
}

// ---------------------------------------------------------------------------
// Stage B helpers
// ---------------------------------------------------------------------------
__device__ __forceinline__ float tanh_fast(float x) {
    float r;
    asm("tanh.approx.f32 %0, %1;" : "=f"(r) : "f"(x));
    return r;
}
__device__ __forceinline__ void ldsm4(unsigned& r0, unsigned& r1,
                                      unsigned& r2, unsigned& r3,
                                      unsigned addr) {
    asm volatile("ldmatrix.sync.aligned.m8n8.x4.shared.b16 {%0,%1,%2,%3}, [%4];"
                 : "=r"(r0), "=r"(r1), "=r"(r2), "=r"(r3) : "r"(addr));
}
__device__ __forceinline__ void mma16816(float* d, const unsigned* a,
                                         unsigned b0, unsigned b1) {
    asm volatile(
        "mma.sync.aligned.m16n8k16.row.col.f32.bf16.bf16.f32 "
        "{%0,%1,%2,%3}, {%4,%5,%6,%7}, {%8,%9}, {%0,%1,%2,%3};"
        : "+f"(d[0]), "+f"(d[1]), "+f"(d[2]), "+f"(d[3])
        : "r"(a[0]), "r"(a[1]), "r"(a[2]), "r"(a[3]), "r"(b0), "r"(b1));
}
__device__ __forceinline__ void cp16(unsigned dst, const void* src) {
    asm volatile("cp.async.ca.shared.global [%0], [%1], 16;"
                 :: "r"(dst), "l"(src));
}

// ---------------------------------------------------------------------------
// Stage B: 128 thr = 4 warps; warp w covers t = w*16..+15, full o=64,
// both signals. cp.async staging, direct-psi correction, bf16 mma.sync.
// ---------------------------------------------------------------------------
__global__ void __launch_bounds__(128, 4) stageB() {
    extern __shared__ char sm[];
    int tid = threadIdx.x;
    int b   = blockIdx.y;
    int t0  = blockIdx.x * TT;
    unsigned sb = (unsigned)__cvta_generic_to_shared(sm);

    // ---- stage W (prepacked bf16) via cp.async: 1024 uint4 ----
    {
        const uint4* src = (const uint4*)g_Wh;
        #pragma unroll
        for (int it = 0; it < 8; ++it) {
            int i = tid + it * 128;          // 0..1023
            int o = i >> 4, q = i & 15;
            cp16(sb + o * ROWB + q * 16, src + i);
        }
    }
    // ---- stage Y tiles via cp.async: 2048 uint4 (32KB) ----
    {
        const uint4* srcP = (const uint4*)(g_Yh + ((size_t)(0 * 4 + b) * TV + t0) * 128);
        const uint4* srcT = (const uint4*)(g_Yh + ((size_t)(1 * 4 + b) * TV + t0) * 128);
        #pragma unroll
        for (int it = 0; it < 16; ++it) {
            int idx = tid + it * 128;        // 0..2047
            int R = idx >> 4, col = idx & 15;
            int sig = R >> 6, tt = R & 63;
            const uint4* src = (sig ? srcT : srcP) + tt * 16 + col;
            cp16(sb + WBYTES + sig * VSIGB + tt * ROWB + col * 16, src);
        }
    }
    asm volatile("cp.async.commit_group;" ::: "memory");
    asm volatile("cp.async.wait_group 0;" ::: "memory");
    __syncthreads();

    // ---- correction: direct psi evaluation, independent per t ----
    {
        int sid = tid >> 6;              // 0 = pred, 1 = target
        int cpi = tid & 63;              // c-pair index
        int dir = cpi >> 5;
        int cA  = (2 * cpi) & 63;
        int pc  = cA >> 1;
        int sp  = sid * 8 + b * 2 + dir;

        const float4* psi4 = (const float4*)g_psi;           // [j*32 + pc]
        const float4* Sf4  = (const float4*)&g_Sf[sp][0][0][0]; // [kk*32 + pc]

        int j0, kk0, kkX;
        bool fwd = (dir == 0);
        if (fwd) {
            j0 = t0 % 1000; kk0 = t0 / 1000;
            kkX = (kk0 + 1 < NCHV) ? kk0 + 1 : NCHV - 1;
        } else {
            int st = 79999 - t0;
            int g = st / 1000;
            j0 = st - g * 1000; kk0 = g - 40;
            kkX = (kk0 > 0) ? kk0 - 1 : 0;
        }
        float4 Sa = Sf4[kk0 * 32 + pc];
        float4 Sb = Sf4[kkX * 32 + pc];

        unsigned* vword = (unsigned*)(sm + WBYTES + sid * VSIGB) + cpi;

        #pragma unroll 4
        for (int tt = 0; tt < TT; ++tt) {
            int j = fwd ? (j0 + tt) : (j0 - tt);
            bool sec = fwd ? (j >= 1000) : (j < 0);
            if (sec) j = fwd ? j - 1000 : j + 1000;
            float sx = sec ? Sb.x : Sa.x, sy = sec ? Sb.y : Sa.y;
            float sz = sec ? Sb.z : Sa.z, sw = sec ? Sb.w : Sa.w;
            float4 p = psi4[j * 32 + pc];
            float hA = p.x * sx - p.y * sy;
            float hB = p.z * sz - p.w * sw;
            unsigned u = vword[tt * (ROWB / 4)];
            float vA = __uint_as_float(u << 16) + hA;
            float vB = __uint_as_float(u & 0xffff0000u) + hB;
            unsigned o;
            asm("cvt.rn.bf16x2.f32 %0, %1, %2;" : "=r"(o) : "f"(vB), "f"(vA));
            vword[tt * (ROWB / 4)] = o;
        }
    }
    __syncthreads();

    // ---- tensor-core GEMM ----
    int w = tid >> 5, lane = tid & 31;
    int tw = w * 16;
    unsigned a_base = sb + (unsigned)(lane & 15) * ROWB
                         + ((lane & 16) ? 16u : 0u);
    unsigned b_base = sb + WBYTES
                    + (unsigned)(tw + (lane & 7) + ((lane & 16) ? 8 : 0)) * ROWB
                    + ((lane & 8) ? 16u : 0u);

    float acc[2][4][2][4];
    #pragma unroll
    for (int s2 = 0; s2 < 2; ++s2)
        #pragma unroll
        for (int m = 0; m < 4; ++m)
            #pragma unroll
            for (int n = 0; n < 2; ++n)
                #pragma unroll
                for (int i = 0; i < 4; ++i) acc[s2][m][n][i] = 0.f;

    #pragma unroll
    for (int k = 0; k < 8; ++k) {
        unsigned a[4][4];
        #pragma unroll
        for (int m = 0; m < 4; ++m)
            ldsm4(a[m][0], a[m][1], a[m][2], a[m][3],
                  a_base + (unsigned)m * (16 * ROWB) + (unsigned)k * 32);
        #pragma unroll
        for (int s2 = 0; s2 < 2; ++s2) {
            unsigned r0, r1, r2, r3;
            ldsm4(r0, r1, r2, r3,
                  b_base + (unsigned)s2 * VSIGB + (unsigned)k * 32);
            #pragma unroll
            for (int m = 0; m < 4; ++m) {
                mma16816(acc[s2][m][0], a[m], r0, r1);
                mma16816(acc[s2][m][1], a[m], r2, r3);
            }
        }
    }

    // ---- epilogue: |tanh(p) - tanh(t)| ----
    float lsum = 0.f;
    #pragma unroll
    for (int m = 0; m < 4; ++m)
        #pragma unroll
        for (int n = 0; n < 2; ++n)
            #pragma unroll
            for (int i = 0; i < 4; ++i)
                lsum += fabsf(tanh_fast(acc[0][m][n][i])
                            - tanh_fast(acc[1][m][n][i]));

    #pragma unroll
    for (int off = 16; off; off >>= 1)
        lsum += __shfl_xor_sync(0xffffffffu, lsum, off);

    __shared__ float red[4];
    if (lane == 0) red[w] = lsum;
    __syncthreads();
    if (tid == 0)
        g_part[b * NTB + blockIdx.x] =
            (double)((red[0] + red[1]) + (red[2] + red[3]));
}

// ---------------------------------------------------------------------------
// Deterministic final reduction -> mean
// ---------------------------------------------------------------------------
__global__ void __launch_bounds__(256) finalize(float* out) {
    __shared__ double sd[256];
    double acc = 0.0;
    for (int i = threadIdx.x; i < NPART; i += 256) acc += g_part[i];
    sd[threadIdx.x] = acc;
    __syncthreads();
    for (int s = 128; s > 0; s >>= 1) {
        if (threadIdx.x < s) sd[threadIdx.x] += sd[threadIdx.x + s];
        __syncthreads();
    }
    if (threadIdx.x == 0)
        out[0] = (float)(sd[0] / (4.0 * 64.0 * 40000.0));
}

// ---------------------------------------------------------------------------
extern "C" void kernel_launch(void* const* d_in, const int* in_sizes, int n_in,
                              void* d_out, int out_size) {
    const float *pred = 0, *targ = 0, *W = 0;
    const void  *cf[3] = { 0, 0, 0 };
    int nBig = 0, nSmall = 0;
    for (int i = 0; i < n_in; ++i) {
        int sz = in_sizes[i];
        if (sz == 480000) {
            if (nBig == 0) pred = (const float*)d_in[i];
            else           targ = (const float*)d_in[i];
            ++nBig;
        } else if (sz == 64 && nSmall < 3) {
            cf[nSmall++] = d_in[i];
        } else if (sz == 8192) {
            W = (const float*)d_in[i];
        }
    }
    float* out = (float*)d_out;

    cudaFuncSetAttribute(stageB, cudaFuncAttributeMaxDynamicSharedMemorySize,
                         SMEM_B);

    prep<<<1, 64>>>(cf[0], cf[1], cf[2], W);
    kphi_pass1<<<8 + (NCHUNK * NSEQ) / 2, 64>>>(pred, targ);
    combine<<<NSEQ, 64>>>();
    stageB<<<dim3(NTB, 4), 128, SMEM_B>>>();
    finalize<<<1, 256>>>(out);
}

// round 13
// speedup vs baseline: 11.7850x; 1.0507x over previous
#include <cuda_runtime.h>
#include <cuda_bf16.h>
#include <math.h>

// ---------------------------------------------------------------------------
// ESpaceLoss: biquad filter bank fwd+bwd -> tanh(W x) -> mean |p - t|
//
//   prep    : value-classified, dtype-robust coefficient load + analytic
//             fp64 reconstruction; W -> bf16; A = M^1000 by binary powering.
//   pass1a  : per (seq,chunk) zero-init fp32 recurrence (double-float
//             coefficients, 12-cyc chain), END STATES ONLY -> g_E.
//   combine : hierarchical 3-phase scan (8 seg x 10 chunks, A^10 jumps)
//             -> exact fp64 init states g_S for chunks 40..79.
//   pass1b  : re-run chunks 40..79 seeded with exact states; writes final
//             corrected bf16 Y directly (no later correction needed).
//   stageB  : cp.async staging + bf16 mma.sync GEMM + tanh.approx |diff|.
//   finalize: deterministic reduction -> scalar mean
// ---------------------------------------------------------------------------

#define TLEN   120000
#define LCH    1000
#define NCHUNK 80
#define CH0    40
#define NCHV   40
#define MARGIN 40000
#define TV     40000
#define NC     64
#define NSEQ   16
#define TT     64          // stage B t-tile
#define NTB    (TV / TT)   // 625
#define NPART  (NTB * 4)   // 2500

#define ROWB   272                     // bf16 tile row stride in bytes (17 lines)
#define WBYTES (64 * ROWB)             // 17408
#define VSIGB  (64 * ROWB)             // 17408 per signal
#define SMEM_B (WBYTES + 2 * VSIGB)    // 52224

__device__ double g_c[3][NC];                  // a1, a2, b0 (normalized fp64)
__device__ double g_A[NC][4];                  // chunk transition M^L
__device__ double g_E[NSEQ][NCHUNK][NC][2];    // particular end states
__device__ double g_S[NSEQ][NCHV][NC][2];      // exact init state (s1,s2)
__device__ unsigned g_Wh[4096];                // W as bf16x2, [o][c-pair]
__device__ __nv_bfloat16 g_Yh[(size_t)2 * 4 * TV * 128]; // [sig][b][t][dir*64+c]
__device__ double g_part[NPART];

// ---------------------------------------------------------------------------
// Coefficient prep + W pack + A = M^1000.
// ---------------------------------------------------------------------------
__device__ __forceinline__ int coeff_class(double v) {
    if (!isfinite(v)) return -1;
    if (v > -2.5 && v < -1.5) return 0;       // a1
    if (v >  0.5 && v <  1.5) return 1;       // a2
    if (v > 1e-7 && v < 1e-2) return 2;       // b0
    return -1;
}

__global__ void __launch_bounds__(64) prep(const void* p0, const void* p1,
                                           const void* p2,
                                           const float* __restrict__ W) {
    const void* bufs[3] = { p0, p1, p2 };
    int c = threadIdx.x;
    __shared__ int slot[3];
    __shared__ int use64;
    __shared__ int mism;

    if (c == 0) {
        int cf[3], cd[3];
        for (int k = 0; k < 3; ++k) {
            cf[k] = coeff_class((double)((const float*)bufs[k])[0]);
            cd[k] = coeff_class(((const double*)bufs[k])[0]);
        }
        bool okf = cf[0] >= 0 && cf[1] >= 0 && cf[2] >= 0 &&
                   cf[0] != cf[1] && cf[0] != cf[2] && cf[1] != cf[2];
        bool okd = cd[0] >= 0 && cd[1] >= 0 && cd[2] >= 0 &&
                   cd[0] != cd[1] && cd[0] != cd[2] && cd[1] != cd[2];
        use64 = okf ? 0 : 1;
        for (int k = 0; k < 3; ++k)
            slot[k] = okf ? cf[k] : (okd ? cd[k] : k);
        mism = 0;
    }
    __syncthreads();

    for (int k = 0; k < 3; ++k) {
        double v = use64 ? ((const double*)bufs[k])[c]
                         : (double)((const float*)bufs[k])[c];
        g_c[slot[k]][c] = v;
    }
    __syncthreads();

    const double PI = 3.14159265358979323846;
    double lmin = log(2.0 * PI * 10.0  / 24000.0);
    double lmax = log(2.0 * PI * 100.0 / 24000.0);
    double th = exp(lmin + (double)c * ((lmax - lmin) / 63.0));
    double r  = 0.9999 + (double)c * ((0.99999 - 0.9999) / 63.0);
    if (c == 63) { th = 2.0 * PI * 100.0 / 24000.0; r = 0.99999; }
    double ra1 = -2.0 * r * cos(th);
    double ra2 = r * r;
    double rb0 = (1.0 - r) * 0.5;

    if (fabs(ra1 - g_c[0][c]) > 1e-5 ||
        fabs(ra2 - g_c[1][c]) > 1e-5 ||
        fabs(rb0 - g_c[2][c]) > 1e-8)
        atomicOr(&mism, 1);
    __syncthreads();

    if (!mism) {
        g_c[0][c] = ra1;
        g_c[1][c] = ra2;
        g_c[2][c] = rb0;
    }
    __syncthreads();

    // A = M^1000, M = [[-a1,-a2],[1,0]], by binary powering (fp64)
    {
        double m00 = -g_c[0][c], m01 = -g_c[1][c];
        double p00 = 1, p01 = 0, p10 = 0, p11 = 1;
        double b00 = m00, b01 = m01, b10 = 1.0, b11 = 0.0;
        int e = 1000;
        while (e) {
            if (e & 1) {
                double t00 = p00 * b00 + p01 * b10, t01 = p00 * b01 + p01 * b11;
                double t10 = p10 * b00 + p11 * b10, t11 = p10 * b01 + p11 * b11;
                p00 = t00; p01 = t01; p10 = t10; p11 = t11;
            }
            e >>= 1;
            if (e) {
                double t00 = b00 * b00 + b01 * b10, t01 = b00 * b01 + b01 * b11;
                double t10 = b10 * b00 + b11 * b10, t11 = b10 * b01 + b11 * b11;
                b00 = t00; b01 = t01; b10 = t10; b11 = t11;
            }
        }
        g_A[c][0] = p00; g_A[c][1] = p01;
        g_A[c][2] = p10; g_A[c][3] = p11;
    }

    // pack W -> bf16x2
    const float2* Wf2 = (const float2*)W;
    for (int i = c; i < 4096; i += 64) {
        float2 wv = Wf2[i];
        unsigned u;
        asm("cvt.rn.bf16x2.f32 %0, %1, %2;" : "=r"(u) : "f"(wv.y), "f"(wv.x));
        g_Wh[i] = u;
    }
}

// ---------------------------------------------------------------------------
// pass1a: zero-init recurrence, end states only. Warp = one (seq,chunk),
// 2 channels/thread, df coefficients with 12-cycle chain.
// ---------------------------------------------------------------------------
__global__ void __launch_bounds__(64) pass1a(
    const float* __restrict__ pred, const float* __restrict__ targ)
{
    __shared__ float xs2[2][LCH];
    int tid = threadIdx.x;
    int w = tid >> 5, l = tid & 31;
    int task = blockIdx.x * 2 + w;           // 0..1279
    int k = task % NCHUNK;
    int s = task / NCHUNK;
    int sig = s >> 3, b = (s >> 1) & 3, dir = s & 1;
    const float* x = (sig ? targ : pred) + b * TLEN;
    float* xs = xs2[w];

    int k0 = k * LCH;
    if (dir == 0) {
        for (int j = l; j < LCH; j += 32) xs[j] = x[k0 + j];
    } else {
        for (int j = l; j < LCH; j += 32) xs[j] = x[TLEN - 1 - (k0 + j)];
    }
    __syncwarp();

    int c0 = 2 * l, c1 = 2 * l + 1;
    double a1A = -g_c[0][c0], a2A = -g_c[1][c0];
    double a1B = -g_c[0][c1], a2B = -g_c[1][c1];
    float n1Ah = (float)a1A, n1Al = (float)(a1A - (double)n1Ah);
    float n2Ah = (float)a2A, n2Al = (float)(a2A - (double)n2Ah);
    float n1Bh = (float)a1B, n1Bl = (float)(a1B - (double)n1Bh);
    float n2Bh = (float)a2B, n2Bl = (float)(a2B - (double)n2Bh);
    float b0A = (float)g_c[2][c0], b0B = (float)g_c[2][c1];

    float y1a = 0.f, y2a = 0.f, y1b = 0.f, y2b = 0.f;
    #pragma unroll 4
    for (int j = 0; j < LCH; ++j) {
        float xj = xs[j];
        float ia = fmaf(n2Al, y2a, b0A * xj);   // off-critical (y2 is old)
        float ta = fmaf(n1Al, y1a, ia);
        float ma = fmaf(n2Ah, y2a, ta);
        float ya = fmaf(n1Ah, y1a, ma);
        float ib = fmaf(n2Bl, y2b, b0B * xj);
        float tb = fmaf(n1Bl, y1b, ib);
        float mb = fmaf(n2Bh, y2b, tb);
        float yb = fmaf(n1Bh, y1b, mb);
        y2a = y1a; y1a = ya;
        y2b = y1b; y1b = yb;
    }
    g_E[s][k][c0][0] = (double)y1a;
    g_E[s][k][c0][1] = (double)y2a;
    g_E[s][k][c1][0] = (double)y1b;
    g_E[s][k][c1][1] = (double)y2b;
}

// ---------------------------------------------------------------------------
// combine: hierarchical scan. 512 thr = (c 0..63, seg 0..7); seg covers 10
// chunks. Phase1: local zero-init scans. Phase2: 8-step boundary scan with
// A^10 (seg==0 threads). Phase3: rescan segments 4..7 from exact boundary
// states, writing g_S for chunks 40..79.
// ---------------------------------------------------------------------------
__global__ void __launch_bounds__(512) combine() {
    __shared__ double Lseg[8][NC][2];
    __shared__ double Sseg[8][NC][2];
    int s   = blockIdx.x;
    int c   = threadIdx.x & 63;
    int seg = threadIdx.x >> 6;

    double A00 = g_A[c][0], A01 = g_A[c][1], A10 = g_A[c][2], A11 = g_A[c][3];

    // prefetch this segment's 10 end-state pairs (MLP=20)
    double e[10][2];
    #pragma unroll
    for (int i = 0; i < 10; ++i) {
        e[i][0] = g_E[s][seg * 10 + i][c][0];
        e[i][1] = g_E[s][seg * 10 + i][c][1];
    }

    // phase 1: local scan from zero
    double l1 = 0.0, l2 = 0.0;
    #pragma unroll
    for (int i = 0; i < 10; ++i) {
        double n1 = fma(A00, l1, fma(A01, l2, e[i][0]));
        double n2 = fma(A10, l1, fma(A11, l2, e[i][1]));
        l1 = n1; l2 = n2;
    }
    Lseg[seg][c][0] = l1;
    Lseg[seg][c][1] = l2;
    __syncthreads();

    // phase 2: boundary scan (seg==0 threads), needs A^10
    if (seg == 0) {
        // A^10 = ((A^2)^2)^2 * A^2
        double B00 = fma(A00, A00, A01 * A10), B01 = fma(A00, A01, A01 * A11);
        double B10 = fma(A10, A00, A11 * A10), B11 = fma(A10, A01, A11 * A11);
        double C00 = fma(B00, B00, B01 * B10), C01 = fma(B00, B01, B01 * B11);
        double C10 = fma(B10, B00, B11 * B10), C11 = fma(B10, B01, B11 * B11);
        double D00 = fma(C00, C00, C01 * C10), D01 = fma(C00, C01, C01 * C11);
        double D10 = fma(C10, C00, C11 * C10), D11 = fma(C10, C01, C11 * C11);
        double T00 = fma(D00, B00, D01 * B10), T01 = fma(D00, B01, D01 * B11);
        double T10 = fma(D10, B00, D11 * B10), T11 = fma(D10, B01, D11 * B11);
        double s1 = 0.0, s2 = 0.0;
        #pragma unroll
        for (int g = 0; g < 8; ++g) {
            Sseg[g][c][0] = s1;
            Sseg[g][c][1] = s2;
            double e1 = Lseg[g][c][0], e2 = Lseg[g][c][1];
            double n1 = fma(T00, s1, fma(T01, s2, e1));
            double n2 = fma(T10, s1, fma(T11, s2, e2));
            s1 = n1; s2 = n2;
        }
    }
    __syncthreads();

    // phase 3: rescan from exact boundary state, emit states for k >= 40
    if (seg >= 4) {
        double s1 = Sseg[seg][c][0], s2 = Sseg[seg][c][1];
        #pragma unroll
        for (int i = 0; i < 10; ++i) {
            int kk = seg * 10 + i - CH0;
            g_S[s][kk][c][0] = s1;
            g_S[s][kk][c][1] = s2;
            double n1 = fma(A00, s1, fma(A01, s2, e[i][0]));
            double n2 = fma(A10, s1, fma(A11, s2, e[i][1]));
            s1 = n1; s2 = n2;
        }
    }
}

// ---------------------------------------------------------------------------
// pass1b: chunks 40..79 with exact init states -> final bf16 Y.
// ---------------------------------------------------------------------------
__global__ void __launch_bounds__(64) pass1b(
    const float* __restrict__ pred, const float* __restrict__ targ)
{
    __shared__ float xs2[2][LCH];
    int tid = threadIdx.x;
    int w = tid >> 5, l = tid & 31;
    int task = blockIdx.x * 2 + w;           // 0..639
    int kk = task % NCHV;
    int s  = task / NCHV;
    int k  = kk + CH0;
    int sig = s >> 3, b = (s >> 1) & 3, dir = s & 1;
    const float* x = (sig ? targ : pred) + b * TLEN;
    float* xs = xs2[w];

    int k0 = k * LCH;
    if (dir == 0) {
        for (int j = l; j < LCH; j += 32) xs[j] = x[k0 + j];
    } else {
        for (int j = l; j < LCH; j += 32) xs[j] = x[TLEN - 1 - (k0 + j)];
    }
    __syncwarp();

    int c0 = 2 * l, c1 = 2 * l + 1;
    double a1A = -g_c[0][c0], a2A = -g_c[1][c0];
    double a1B = -g_c[0][c1], a2B = -g_c[1][c1];
    float n1Ah = (float)a1A, n1Al = (float)(a1A - (double)n1Ah);
    float n2Ah = (float)a2A, n2Al = (float)(a2A - (double)n2Ah);
    float n1Bh = (float)a1B, n1Bl = (float)(a1B - (double)n1Bh);
    float n2Bh = (float)a2B, n2Bl = (float)(a2B - (double)n2Bh);
    float b0A = (float)g_c[2][c0], b0B = (float)g_c[2][c1];

    float y1a = (float)g_S[s][kk][c0][0], y2a = (float)g_S[s][kk][c0][1];
    float y1b = (float)g_S[s][kk][c1][0], y2b = (float)g_S[s][kk][c1][1];

    unsigned* yrow = (unsigned*)(g_Yh
        + (size_t)((sig * 4 + b) * TV) * 128 + dir * 64 + c0);
    int tl0 = dir ? (TLEN - 1 - MARGIN - k0) : (k0 - MARGIN);
    int tstep = dir ? -1 : 1;

    #pragma unroll 4
    for (int j = 0; j < LCH; ++j) {
        float xj = xs[j];
        float ia = fmaf(n2Al, y2a, b0A * xj);
        float ta = fmaf(n1Al, y1a, ia);
        float ma = fmaf(n2Ah, y2a, ta);
        float ya = fmaf(n1Ah, y1a, ma);
        float ib = fmaf(n2Bl, y2b, b0B * xj);
        float tb = fmaf(n1Bl, y1b, ib);
        float mb = fmaf(n2Bh, y2b, tb);
        float yb = fmaf(n1Bh, y1b, mb);
        unsigned o;
        asm("cvt.rn.bf16x2.f32 %0, %1, %2;" : "=r"(o) : "f"(yb), "f"(ya));
        yrow[(size_t)(tl0 + j * tstep) * 64] = o;
        y2a = y1a; y1a = ya;
        y2b = y1b; y1b = yb;
    }
}

// ---------------------------------------------------------------------------
// Stage B helpers
// ---------------------------------------------------------------------------
__device__ __forceinline__ float tanh_fast(float x) {
    float r;
    asm("tanh.approx.f32 %0, %1;" : "=f"(r) : "f"(x));
    return r;
}
__device__ __forceinline__ void ldsm4(unsigned& r0, unsigned& r1,
                                      unsigned& r2, unsigned& r3,
                                      unsigned addr) {
    asm volatile("ldmatrix.sync.aligned.m8n8.x4.shared.b16 {%0,%1,%2,%3}, [%4];"
                 : "=r"(r0), "=r"(r1), "=r"(r2), "=r"(r3) : "r"(addr));
}
__device__ __forceinline__ void mma16816(float* d, const unsigned* a,
                                         unsigned b0, unsigned b1) {
    asm volatile(
        "mma.sync.aligned.m16n8k16.row.col.f32.bf16.bf16.f32 "
        "{%0,%1,%2,%3}, {%4,%5,%6,%7}, {%8,%9}, {%0,%1,%2,%3};"
        : "+f"(d[0]), "+f"(d[1]), "+f"(d[2]), "+f"(d[3])
        : "r"(a[0]), "r"(a[1]), "r"(a[2]), "r"(a[3]), "r"(b0), "r"(b1));
}
__device__ __forceinline__ void cp16(unsigned dst, const void* src) {
    asm volatile("cp.async.ca.shared.global [%0], [%1], 16;"
                 :: "r"(dst), "l"(src));
}

// ---------------------------------------------------------------------------
// Stage B: staging + GEMM + epilogue only (Y is already fully corrected).
// ---------------------------------------------------------------------------
__global__ void __launch_bounds__(128, 4) stageB() {
    extern __shared__ char sm[];
    int tid = threadIdx.x;
    int b   = blockIdx.y;
    int t0  = blockIdx.x * TT;
    unsigned sb = (unsigned)__cvta_generic_to_shared(sm);

    // ---- stage W (prepacked bf16) via cp.async: 1024 uint4 ----
    {
        const uint4* src = (const uint4*)g_Wh;
        #pragma unroll
        for (int it = 0; it < 8; ++it) {
            int i = tid + it * 128;
            int o = i >> 4, q = i & 15;
            cp16(sb + o * ROWB + q * 16, src + i);
        }
    }
    // ---- stage Y tiles via cp.async: 2048 uint4 (32KB) ----
    {
        const uint4* srcP = (const uint4*)(g_Yh + ((size_t)(0 * 4 + b) * TV + t0) * 128);
        const uint4* srcT = (const uint4*)(g_Yh + ((size_t)(1 * 4 + b) * TV + t0) * 128);
        #pragma unroll
        for (int it = 0; it < 16; ++it) {
            int idx = tid + it * 128;
            int R = idx >> 4, col = idx & 15;
            int sig = R >> 6, tt = R & 63;
            const uint4* src = (sig ? srcT : srcP) + tt * 16 + col;
            cp16(sb + WBYTES + sig * VSIGB + tt * ROWB + col * 16, src);
        }
    }
    asm volatile("cp.async.commit_group;" ::: "memory");
    asm volatile("cp.async.wait_group 0;" ::: "memory");
    __syncthreads();

    // ---- tensor-core GEMM ----
    int w = tid >> 5, lane = tid & 31;
    int tw = w * 16;
    unsigned a_base = sb + (unsigned)(lane & 15) * ROWB
                         + ((lane & 16) ? 16u : 0u);
    unsigned b_base = sb + WBYTES
                    + (unsigned)(tw + (lane & 7) + ((lane & 16) ? 8 : 0)) * ROWB
                    + ((lane & 8) ? 16u : 0u);

    float acc[2][4][2][4];
    #pragma unroll
    for (int s2 = 0; s2 < 2; ++s2)
        #pragma unroll
        for (int m = 0; m < 4; ++m)
            #pragma unroll
            for (int n = 0; n < 2; ++n)
                #pragma unroll
                for (int i = 0; i < 4; ++i) acc[s2][m][n][i] = 0.f;

    #pragma unroll
    for (int k = 0; k < 8; ++k) {
        unsigned a[4][4];
        #pragma unroll
        for (int m = 0; m < 4; ++m)
            ldsm4(a[m][0], a[m][1], a[m][2], a[m][3],
                  a_base + (unsigned)m * (16 * ROWB) + (unsigned)k * 32);
        #pragma unroll
        for (int s2 = 0; s2 < 2; ++s2) {
            unsigned r0, r1, r2, r3;
            ldsm4(r0, r1, r2, r3,
                  b_base + (unsigned)s2 * VSIGB + (unsigned)k * 32);
            #pragma unroll
            for (int m = 0; m < 4; ++m) {
                mma16816(acc[s2][m][0], a[m], r0, r1);
                mma16816(acc[s2][m][1], a[m], r2, r3);
            }
        }
    }

    // ---- epilogue: |tanh(p) - tanh(t)| ----
    float lsum = 0.f;
    #pragma unroll
    for (int m = 0; m < 4; ++m)
        #pragma unroll
        for (int n = 0; n < 2; ++n)
            #pragma unroll
            for (int i = 0; i < 4; ++i)
                lsum += fabsf(tanh_fast(acc[0][m][n][i])
                            - tanh_fast(acc[1][m][n][i]));

    #pragma unroll
    for (int off = 16; off; off >>= 1)
        lsum += __shfl_xor_sync(0xffffffffu, lsum, off);

    __shared__ float red[4];
    if (lane == 0) red[w] = lsum;
    __syncthreads();
    if (tid == 0)
        g_part[b * NTB + blockIdx.x] =
            (double)((red[0] + red[1]) + (red[2] + red[3]));
}

// ---------------------------------------------------------------------------
// Deterministic final reduction -> mean
// ---------------------------------------------------------------------------
__global__ void __launch_bounds__(256) finalize(float* out) {
    __shared__ double sd[256];
    double acc = 0.0;
    for (int i = threadIdx.x; i < NPART; i += 256) acc += g_part[i];
    sd[threadIdx.x] = acc;
    __syncthreads();
    for (int s = 128; s > 0; s >>= 1) {
        if (threadIdx.x < s) sd[threadIdx.x] += sd[threadIdx.x + s];
        __syncthreads();
    }
    if (threadIdx.x == 0)
        out[0] = (float)(sd[0] / (4.0 * 64.0 * 40000.0));
}

// ---------------------------------------------------------------------------
extern "C" void kernel_launch(void* const* d_in, const int* in_sizes, int n_in,
                              void* d_out, int out_size) {
    const float *pred = 0, *targ = 0, *W = 0;
    const void  *cf[3] = { 0, 0, 0 };
    int nBig = 0, nSmall = 0;
    for (int i = 0; i < n_in; ++i) {
        int sz = in_sizes[i];
        if (sz == 480000) {
            if (nBig == 0) pred = (const float*)d_in[i];
            else           targ = (const float*)d_in[i];
            ++nBig;
        } else if (sz == 64 && nSmall < 3) {
            cf[nSmall++] = d_in[i];
        } else if (sz == 8192) {
            W = (const float*)d_in[i];
        }
    }
    float* out = (float*)d_out;

    cudaFuncSetAttribute(stageB, cudaFuncAttributeMaxDynamicSharedMemorySize,
                         SMEM_B);

    prep<<<1, 64>>>(cf[0], cf[1], cf[2], W);
    pass1a<<<(NCHUNK * NSEQ) / 2, 64>>>(pred, targ);
    combine<<<NSEQ, 512>>>();
    pass1b<<<(NCHV * NSEQ) / 2, 64>>>(pred, targ);
    stageB<<<dim3(NTB, 4), 128, SMEM_B>>>();
    finalize<<<1, 256>>>(out);
}